// round 1
// baseline (speedup 1.0000x reference)
#include <cuda_runtime.h>
#include <cstdint>

#define SCALE 0.125f

// Scratch (alloc-free rule: module-level device globals)
__device__ float g_qkv[25165824]; // 8192 x 3072  (q|k|v interleaved along last dim)
__device__ float g_ao[8388608];   // 8192 x 1024  (attention output, [B,N,C])

// ---------------- packed f32x2 helpers (FFMA2 path, sm_100+) ----------------
__device__ __forceinline__ unsigned long long pk2(float lo, float hi) {
    unsigned long long r;
    asm("mov.b64 %0, {%1, %2};" : "=l"(r) : "f"(lo), "f"(hi));
    return r;
}
__device__ __forceinline__ void upk2(unsigned long long v, float& lo, float& hi) {
    asm("mov.b64 {%0, %1}, %2;" : "=f"(lo), "=f"(hi) : "l"(v));
}
__device__ __forceinline__ unsigned long long ffma2(unsigned long long a,
                                                    unsigned long long b,
                                                    unsigned long long c) {
    unsigned long long d;
    asm("fma.rn.f32x2 %0, %1, %2, %3;" : "=l"(d) : "l"(a), "l"(b), "l"(c));
    return d;
}
__device__ __forceinline__ unsigned long long fmul2(unsigned long long a,
                                                    unsigned long long b) {
    unsigned long long d;
    asm("mul.rn.f32x2 %0, %1, %2;" : "=l"(d) : "l"(a), "l"(b));
    return d;
}

// ---------------- SGEMM-NT core: C[M,N] = A[M,K] * B[N,K]^T (+bias) ----------
// 128x128 block tile, BK=16, 256 threads, 8x8 micro-tile (as 4x f32x2 per row).
template <int M, int N, int K, bool HAS_BIAS>
__device__ __forceinline__ void sgemm_core(const float* __restrict__ A,
                                           const float* __restrict__ Bm,
                                           float* __restrict__ Cm,
                                           const float* __restrict__ bias) {
    __shared__ __align__(16) float As[16][132];
    __shared__ __align__(16) float Bs[16][132];
    const int tid = threadIdx.x;
    const int tx = tid & 15, ty = tid >> 4;
    const int bn = blockIdx.x * 128;
    const int bm = blockIdx.y * 128;
    const int lrow = tid >> 2;          // 0..63
    const int lcol = (tid & 3) << 2;    // 0,4,8,12

    const float* At = A + (size_t)(bm + lrow) * K + lcol;
    const float* Bt = Bm + (size_t)(bn + lrow) * K + lcol;

    unsigned long long acc[8][4];
#pragma unroll
    for (int i = 0; i < 8; i++)
#pragma unroll
        for (int j = 0; j < 4; j++) acc[i][j] = 0ULL;

    float4 pa0 = *(const float4*)At;
    float4 pa1 = *(const float4*)(At + (size_t)64 * K);
    float4 pb0 = *(const float4*)Bt;
    float4 pb1 = *(const float4*)(Bt + (size_t)64 * K);

    for (int kt = 0; kt < K; kt += 16) {
        As[lcol + 0][lrow] = pa0.x; As[lcol + 1][lrow] = pa0.y;
        As[lcol + 2][lrow] = pa0.z; As[lcol + 3][lrow] = pa0.w;
        As[lcol + 0][lrow + 64] = pa1.x; As[lcol + 1][lrow + 64] = pa1.y;
        As[lcol + 2][lrow + 64] = pa1.z; As[lcol + 3][lrow + 64] = pa1.w;
        Bs[lcol + 0][lrow] = pb0.x; Bs[lcol + 1][lrow] = pb0.y;
        Bs[lcol + 2][lrow] = pb0.z; Bs[lcol + 3][lrow] = pb0.w;
        Bs[lcol + 0][lrow + 64] = pb1.x; Bs[lcol + 1][lrow + 64] = pb1.y;
        Bs[lcol + 2][lrow + 64] = pb1.z; Bs[lcol + 3][lrow + 64] = pb1.w;
        __syncthreads();

        if (kt + 16 < K) {  // prefetch next tile into registers
            At += 16; Bt += 16;
            pa0 = *(const float4*)At;
            pa1 = *(const float4*)(At + (size_t)64 * K);
            pb0 = *(const float4*)Bt;
            pb1 = *(const float4*)(Bt + (size_t)64 * K);
        }

#pragma unroll
        for (int k = 0; k < 16; k++) {
            float4 ta0 = *(const float4*)&As[k][ty * 4];
            float4 ta1 = *(const float4*)&As[k][ty * 4 + 64];
            float4 tb0 = *(const float4*)&Bs[k][tx * 4];
            float4 tb1 = *(const float4*)&Bs[k][tx * 4 + 64];
            unsigned long long bp0 = pk2(tb0.x, tb0.y), bp1 = pk2(tb0.z, tb0.w);
            unsigned long long bp2 = pk2(tb1.x, tb1.y), bp3 = pk2(tb1.z, tb1.w);
            float av[8] = {ta0.x, ta0.y, ta0.z, ta0.w, ta1.x, ta1.y, ta1.z, ta1.w};
#pragma unroll
            for (int i = 0; i < 8; i++) {
                unsigned long long ad = pk2(av[i], av[i]);
                acc[i][0] = ffma2(ad, bp0, acc[i][0]);
                acc[i][1] = ffma2(ad, bp1, acc[i][1]);
                acc[i][2] = ffma2(ad, bp2, acc[i][2]);
                acc[i][3] = ffma2(ad, bp3, acc[i][3]);
            }
        }
        __syncthreads();
    }

#pragma unroll
    for (int i = 0; i < 8; i++) {
        const int m = bm + ((i < 4) ? (ty * 4 + i) : (64 + ty * 4 + i - 4));
        float c[8];
        upk2(acc[i][0], c[0], c[1]); upk2(acc[i][1], c[2], c[3]);
        upk2(acc[i][2], c[4], c[5]); upk2(acc[i][3], c[6], c[7]);
        const int n0 = bn + tx * 4, n1 = bn + 64 + tx * 4;
        if (HAS_BIAS) {
            float4 b0 = *(const float4*)&bias[n0];
            float4 b1 = *(const float4*)&bias[n1];
            c[0] += b0.x; c[1] += b0.y; c[2] += b0.z; c[3] += b0.w;
            c[4] += b1.x; c[5] += b1.y; c[6] += b1.z; c[7] += b1.w;
        }
        *(float4*)&Cm[(size_t)m * N + n0] = make_float4(c[0], c[1], c[2], c[3]);
        *(float4*)&Cm[(size_t)m * N + n1] = make_float4(c[4], c[5], c[6], c[7]);
    }
}

__global__ __launch_bounds__(256) void k_qkv(const float* __restrict__ x,
                                             const float* __restrict__ w) {
    sgemm_core<8192, 3072, 1024, false>(x, w, g_qkv, nullptr);
}
__global__ __launch_bounds__(256) void k_proj(const float* __restrict__ w,
                                              const float* __restrict__ bias,
                                              float* __restrict__ out) {
    sgemm_core<8192, 1024, 1024, true>(g_ao, w, out, bias);
}

// ---------------- Flash attention, fp32, 64-row q tile, full KV sweep --------
// 128 threads: tx = tid&15 owns 4 HD cols, ty = tid>>4 owns 8 q rows.
__global__ __launch_bounds__(128) void k_attn() {
    __shared__ __align__(16) float Qs[64][64];  // Q^T  [d][r], pre-scaled
    __shared__ __align__(16) float KP[64][64];  // K^T [d][j], then P^T [j][r]
    __shared__ __align__(16) float Vs[64][64];  // V   [j][d]
    const int tid = threadIdx.x;
    const int tx = tid & 15, ty = tid >> 4;
    const int bh = blockIdx.y;                  // b*16 + h
    const int q0 = blockIdx.x * 64;
    const float* qbase = g_qkv + (size_t)(bh >> 4) * 2048 * 3072 + (bh & 15) * 64;
    const float* kbase = qbase + 1024;
    const float* vbase = qbase + 2048;

    {   // load Q tile, scaled + transposed
        const int r = tid >> 1;
        const int d0 = (tid & 1) * 4;
        const float* src = qbase + (size_t)(q0 + r) * 3072 + d0;
#pragma unroll
        for (int u = 0; u < 8; u++) {
            float4 f = *(const float4*)(src + u * 8);
            int d = d0 + u * 8;
            Qs[d + 0][r] = f.x * SCALE; Qs[d + 1][r] = f.y * SCALE;
            Qs[d + 2][r] = f.z * SCALE; Qs[d + 3][r] = f.w * SCALE;
        }
    }

    unsigned long long op[8][2];
    float mrun[8], lrun[8];
#pragma unroll
    for (int i = 0; i < 8; i++) {
        op[i][0] = 0ULL; op[i][1] = 0ULL;
        mrun[i] = -3.0e38f; lrun[i] = 0.f;
    }
    __syncthreads();

    for (int t = 0; t < 2048; t += 64) {
        {   // load K (transposed) + V (natural)
            const int r = tid >> 1;
            const int d0 = (tid & 1) * 4;
            const float* ks = kbase + (size_t)(t + r) * 3072 + d0;
            const float* vs = vbase + (size_t)(t + r) * 3072 + d0;
#pragma unroll
            for (int u = 0; u < 8; u++) {
                float4 f = *(const float4*)(ks + u * 8);
                float4 g = *(const float4*)(vs + u * 8);
                int d = d0 + u * 8;
                KP[d + 0][r] = f.x; KP[d + 1][r] = f.y;
                KP[d + 2][r] = f.z; KP[d + 3][r] = f.w;
                *(float4*)&Vs[r][d] = g;
            }
        }
        __syncthreads();

        // S = (Q*scale) K^T  — rows ty*8..+7, cols tx*4..+3
        unsigned long long sp[8][2];
#pragma unroll
        for (int i = 0; i < 8; i++) { sp[i][0] = 0ULL; sp[i][1] = 0ULL; }
#pragma unroll 8
        for (int d = 0; d < 64; d++) {
            float4 a0 = *(const float4*)&Qs[d][ty * 8];
            float4 a1 = *(const float4*)&Qs[d][ty * 8 + 4];
            float4 bq = *(const float4*)&KP[d][tx * 4];
            unsigned long long b0 = pk2(bq.x, bq.y), b1 = pk2(bq.z, bq.w);
            float av[8] = {a0.x, a0.y, a0.z, a0.w, a1.x, a1.y, a1.z, a1.w};
#pragma unroll
            for (int i = 0; i < 8; i++) {
                unsigned long long ad = pk2(av[i], av[i]);
                sp[i][0] = ffma2(ad, b0, sp[i][0]);
                sp[i][1] = ffma2(ad, b1, sp[i][1]);
            }
        }

        float s[8][4];
#pragma unroll
        for (int i = 0; i < 8; i++) {
            upk2(sp[i][0], s[i][0], s[i][1]);
            upk2(sp[i][1], s[i][2], s[i][3]);
        }

        // online softmax (row stats across the 16-lane tx group)
#pragma unroll
        for (int i = 0; i < 8; i++) {
            float tm = fmaxf(fmaxf(s[i][0], s[i][1]), fmaxf(s[i][2], s[i][3]));
            tm = fmaxf(tm, __shfl_xor_sync(0xffffffffu, tm, 1));
            tm = fmaxf(tm, __shfl_xor_sync(0xffffffffu, tm, 2));
            tm = fmaxf(tm, __shfl_xor_sync(0xffffffffu, tm, 4));
            tm = fmaxf(tm, __shfl_xor_sync(0xffffffffu, tm, 8));
            float mnew = fmaxf(mrun[i], tm);
            float alpha = __expf(mrun[i] - mnew);
            mrun[i] = mnew;
            float ls = 0.f;
#pragma unroll
            for (int j = 0; j < 4; j++) {
                s[i][j] = __expf(s[i][j] - mnew);
                ls += s[i][j];
            }
            ls += __shfl_xor_sync(0xffffffffu, ls, 1);
            ls += __shfl_xor_sync(0xffffffffu, ls, 2);
            ls += __shfl_xor_sync(0xffffffffu, ls, 4);
            ls += __shfl_xor_sync(0xffffffffu, ls, 8);
            lrun[i] = lrun[i] * alpha + ls;
            unsigned long long ap = pk2(alpha, alpha);
            op[i][0] = fmul2(op[i][0], ap);
            op[i][1] = fmul2(op[i][1], ap);
        }

        __syncthreads();  // all threads done reading K half of KP
        // store P^T into KP: KP[j][r] = p[r][j]
#pragma unroll
        for (int jj = 0; jj < 4; jj++) {
            *(float4*)&KP[tx * 4 + jj][ty * 8] =
                make_float4(s[0][jj], s[1][jj], s[2][jj], s[3][jj]);
            *(float4*)&KP[tx * 4 + jj][ty * 8 + 4] =
                make_float4(s[4][jj], s[5][jj], s[6][jj], s[7][jj]);
        }
        __syncthreads();

        // O += P V
#pragma unroll 8
        for (int j = 0; j < 64; j++) {
            float4 a0 = *(const float4*)&KP[j][ty * 8];
            float4 a1 = *(const float4*)&KP[j][ty * 8 + 4];
            float4 vv = *(const float4*)&Vs[j][tx * 4];
            unsigned long long b0 = pk2(vv.x, vv.y), b1 = pk2(vv.z, vv.w);
            float av[8] = {a0.x, a0.y, a0.z, a0.w, a1.x, a1.y, a1.z, a1.w};
#pragma unroll
            for (int i = 0; i < 8; i++) {
                unsigned long long ad = pk2(av[i], av[i]);
                op[i][0] = ffma2(ad, b0, op[i][0]);
                op[i][1] = ffma2(ad, b1, op[i][1]);
            }
        }
        __syncthreads();  // before next tile overwrites KP/Vs
    }

    // normalize + write to [B,N,C] layout (c = h*64 + hd)
    float* dst = g_ao + (size_t)((bh >> 4) * 2048 + q0) * 1024 + (bh & 15) * 64 + tx * 4;
#pragma unroll
    for (int i = 0; i < 8; i++) {
        float inv = 1.0f / lrun[i];
        float o0, o1, o2, o3;
        upk2(op[i][0], o0, o1);
        upk2(op[i][1], o2, o3);
        *(float4*)&dst[(size_t)(ty * 8 + i) * 1024] =
            make_float4(o0 * inv, o1 * inv, o2 * inv, o3 * inv);
    }
}

// ---------------- launch ----------------
extern "C" void kernel_launch(void* const* d_in, const int* in_sizes, int n_in,
                              void* d_out, int out_size) {
    (void)in_sizes; (void)n_in; (void)out_size;
    const float* x      = (const float*)d_in[0];
    const float* w_qkv  = (const float*)d_in[1];
    const float* w_proj = (const float*)d_in[2];
    const float* b_proj = (const float*)d_in[3];
    float* out = (float*)d_out;

    k_qkv<<<dim3(24, 64), 256>>>(x, w_qkv);      // qkv = x @ w_qkv^T
    k_attn<<<dim3(32, 64), 128>>>();             // per-head flash attention
    k_proj<<<dim3(8, 64), 256>>>(w_proj, b_proj, out);  // out = ao @ w_proj^T + b
}

// round 3
// speedup vs baseline: 2.1775x; 2.1775x over previous
#include <cuda_runtime.h>
#include <cuda_bf16.h>
#include <cstdint>

#define SCALE 0.125f
#define SWZ128(o) ((o) ^ (((o) >> 3) & 0x70))

// ---------------- scratch (alloc-free rule: module-level device globals) ----
__device__ float g_qkv[25165824];            // 8192 x 3072 f32 (qkv GEMM out)
__device__ float g_ao[8388608];              // 8192 x 1024 f32 (attn out)
__device__ __nv_bfloat16 g_xs[25165824];     // 8192 x 3072  x split  [Ah|Ah|Al]
__device__ __nv_bfloat16 g_ws[9437184];      // 3072 x 3072  w_qkv split [Bh|Bl|Bh]
__device__ __nv_bfloat16 g_wp[3145728];      // 1024 x 3072  w_proj split
__device__ __nv_bfloat16 g_aos[25165824];    // 8192 x 3072  attn-out split
__device__ __nv_bfloat16 g_qkvh[25165824];   // qkv hi bf16
__device__ __nv_bfloat16 g_qkvl[25165824];   // qkv lo bf16

// ---------------- helpers ----------------
__device__ __forceinline__ uint32_t smem_u32(const void* p) {
    uint32_t a;
    asm("{ .reg .u64 t; cvta.to.shared.u64 t, %1; cvt.u32.u64 %0, t; }" : "=r"(a) : "l"(p));
    return a;
}
__device__ __forceinline__ void ldsm4(uint32_t& r0, uint32_t& r1, uint32_t& r2,
                                      uint32_t& r3, uint32_t a) {
    asm volatile("ldmatrix.sync.aligned.m8n8.x4.shared.b16 {%0,%1,%2,%3},[%4];"
                 : "=r"(r0), "=r"(r1), "=r"(r2), "=r"(r3) : "r"(a));
}
__device__ __forceinline__ void ldsm4t(uint32_t& r0, uint32_t& r1, uint32_t& r2,
                                       uint32_t& r3, uint32_t a) {
    asm volatile("ldmatrix.sync.aligned.m8n8.x4.trans.shared.b16 {%0,%1,%2,%3},[%4];"
                 : "=r"(r0), "=r"(r1), "=r"(r2), "=r"(r3) : "r"(a));
}
__device__ __forceinline__ void sts128(uint32_t a, uint4 v) {
    asm volatile("st.shared.v4.b32 [%0], {%1,%2,%3,%4};"
                 :: "r"(a), "r"(v.x), "r"(v.y), "r"(v.z), "r"(v.w) : "memory");
}
__device__ __forceinline__ void mma16816(float* c, const uint32_t* a,
                                         uint32_t b0, uint32_t b1) {
    asm volatile(
        "mma.sync.aligned.m16n8k16.row.col.f32.bf16.bf16.f32 "
        "{%0,%1,%2,%3},{%4,%5,%6,%7},{%8,%9},{%0,%1,%2,%3};"
        : "+f"(c[0]), "+f"(c[1]), "+f"(c[2]), "+f"(c[3])
        : "r"(a[0]), "r"(a[1]), "r"(a[2]), "r"(a[3]), "r"(b0), "r"(b1));
}
// pack 2 f32 -> bf16x2 (elem0 in low half)
__device__ __forceinline__ uint32_t cvt2(float f0, float f1) {
    uint32_t r;
    asm("cvt.rn.bf16x2.f32 %0, %1, %2;" : "=r"(r) : "f"(f1), "f"(f0));
    return r;
}
__device__ __forceinline__ void mkfrag(uint32_t& h, uint32_t& l, float f0, float f1) {
    h = cvt2(f0, f1);
    float r0 = f0 - __uint_as_float(h << 16);
    float r1 = f1 - __uint_as_float(h & 0xffff0000u);
    l = cvt2(r0, r1);
}

// ---------------- split kernels: f32 -> [hi|hi|lo] or [hi|lo|hi] bf16 --------
__device__ __forceinline__ void split_core(const float* __restrict__ src,
                                           __nv_bfloat16* __restrict__ dst,
                                           bool bpat) {
    long i = (long)blockIdx.x * 256 + threadIdx.x;
    long r = i >> 9;
    int k2 = (int)(i & 511) << 1;
    float2 v = *(const float2*)(src + r * 1024 + k2);
    __nv_bfloat16 h0 = __float2bfloat16(v.x), h1 = __float2bfloat16(v.y);
    __nv_bfloat16 l0 = __float2bfloat16(v.x - __bfloat162float(h0));
    __nv_bfloat16 l1 = __float2bfloat16(v.y - __bfloat162float(h1));
    __nv_bfloat162 hh = __halves2bfloat162(h0, h1);
    __nv_bfloat162 ll = __halves2bfloat162(l0, l1);
    __nv_bfloat16* base = dst + r * 3072 + k2;
    *(__nv_bfloat162*)(base) = hh;
    *(__nv_bfloat162*)(base + 1024) = bpat ? ll : hh;
    *(__nv_bfloat162*)(base + 2048) = bpat ? hh : ll;
}
__global__ __launch_bounds__(256) void k_split_x(const float* __restrict__ s) {
    split_core(s, g_xs, false);
}
__global__ __launch_bounds__(256) void k_split_wqkv(const float* __restrict__ s) {
    split_core(s, g_ws, true);
}
__global__ __launch_bounds__(256) void k_split_wproj(const float* __restrict__ s) {
    split_core(s, g_wp, true);
}
__global__ __launch_bounds__(256) void k_split_ao() {
    split_core(g_ao, g_aos, false);
}
// qkv f32 -> hi/lo bf16 planes (for attention)
__global__ __launch_bounds__(256) void k_split_qkv() {
    size_t i = ((size_t)blockIdx.x * 256 + threadIdx.x) * 4;
    float4 v = *(const float4*)(g_qkv + i);
    uint32_t h01, l01, h23, l23;
    mkfrag(h01, l01, v.x, v.y);
    mkfrag(h23, l23, v.z, v.w);
    *(uint2*)(g_qkvh + i) = make_uint2(h01, h23);
    *(uint2*)(g_qkvl + i) = make_uint2(l01, l23);
}

// ---------------- mma.sync GEMM: C[M,N] = A'[M,3072] * B'[N,3072]^T ----------
// 128x128 CTA tile, 8 warps (2x4), BK=32, reg-staged double buffer.
template <int NCOL, bool HAS_BIAS>
__device__ __forceinline__ void gemm_core(const __nv_bfloat16* __restrict__ A,
                                          const __nv_bfloat16* __restrict__ B,
                                          float* __restrict__ C,
                                          const float* __restrict__ bias) {
    constexpr int KT = 3072;
    __shared__ __align__(16) __nv_bfloat16 As[2][128][40];
    __shared__ __align__(16) __nv_bfloat16 Bs[2][128][40];
    const int tid = threadIdx.x, lane = tid & 31, wid = tid >> 5;
    const int wr = wid >> 2, wc = wid & 3;
    const int bm = blockIdx.y * 128, bn = blockIdx.x * 128;

    const int r0 = tid >> 2, cc = (tid & 3) * 8;
    const __nv_bfloat16* Ap = A + (size_t)(bm + r0) * KT + cc;
    const __nv_bfloat16* Bp = B + (size_t)(bn + r0) * KT + cc;
    const size_t roff = (size_t)64 * KT;

    float acc[4][4][4];
#pragma unroll
    for (int i = 0; i < 4; i++)
#pragma unroll
        for (int j = 0; j < 4; j++)
#pragma unroll
            for (int q = 0; q < 4; q++) acc[i][j][q] = 0.f;

    uint4 pa0 = *(const uint4*)Ap, pa1 = *(const uint4*)(Ap + roff);
    uint4 pb0 = *(const uint4*)Bp, pb1 = *(const uint4*)(Bp + roff);
    *(uint4*)&As[0][r0][cc] = pa0;
    *(uint4*)&As[0][r0 + 64][cc] = pa1;
    *(uint4*)&Bs[0][r0][cc] = pb0;
    *(uint4*)&Bs[0][r0 + 64][cc] = pb1;
    __syncthreads();

    for (int it = 0; it < 96; it++) {
        const int cur = it & 1;
        if (it + 1 < 96) {
            const __nv_bfloat16* a2 = Ap + (it + 1) * 32;
            const __nv_bfloat16* b2 = Bp + (it + 1) * 32;
            pa0 = *(const uint4*)a2; pa1 = *(const uint4*)(a2 + roff);
            pb0 = *(const uint4*)b2; pb1 = *(const uint4*)(b2 + roff);
        }
#pragma unroll
        for (int k16 = 0; k16 < 2; k16++) {
            const int ka = k16 * 16 + ((lane & 16) ? 8 : 0);
            uint32_t af[4][4];
#pragma unroll
            for (int mt = 0; mt < 4; mt++) {
                const int rr = wr * 64 + mt * 16 + (lane & 15);
                ldsm4(af[mt][0], af[mt][1], af[mt][2], af[mt][3],
                      smem_u32(&As[cur][rr][ka]));
            }
            const int kb = k16 * 16 + ((lane & 8) ? 8 : 0);
#pragma unroll
            for (int p = 0; p < 2; p++) {
                const int nr = wc * 32 + p * 16 + (lane & 7) + ((lane & 16) ? 8 : 0);
                uint32_t b0, b1, b2, b3;
                ldsm4(b0, b1, b2, b3, smem_u32(&Bs[cur][nr][kb]));
#pragma unroll
                for (int mt = 0; mt < 4; mt++) {
                    mma16816(acc[mt][2 * p], af[mt], b0, b1);
                    mma16816(acc[mt][2 * p + 1], af[mt], b2, b3);
                }
            }
        }
        if (it + 1 < 96) {
            const int nxt = cur ^ 1;
            *(uint4*)&As[nxt][r0][cc] = pa0;
            *(uint4*)&As[nxt][r0 + 64][cc] = pa1;
            *(uint4*)&Bs[nxt][r0][cc] = pb0;
            *(uint4*)&Bs[nxt][r0 + 64][cc] = pb1;
        }
        __syncthreads();
    }

#pragma unroll
    for (int mt = 0; mt < 4; mt++) {
        const int row = bm + wr * 64 + mt * 16 + (lane >> 2);
#pragma unroll
        for (int nt = 0; nt < 4; nt++) {
            const int col = bn + wc * 32 + nt * 8 + (lane & 3) * 2;
            float b0v = 0.f, b1v = 0.f;
            if (HAS_BIAS) { b0v = __ldg(&bias[col]); b1v = __ldg(&bias[col + 1]); }
            *(float2*)&C[(size_t)row * NCOL + col] =
                make_float2(acc[mt][nt][0] + b0v, acc[mt][nt][1] + b1v);
            *(float2*)&C[(size_t)(row + 8) * NCOL + col] =
                make_float2(acc[mt][nt][2] + b0v, acc[mt][nt][3] + b1v);
        }
    }
}

__global__ __launch_bounds__(256) void k_gemm_qkv() {
    gemm_core<3072, false>(g_xs, g_ws, g_qkv, nullptr);
}
__global__ __launch_bounds__(256) void k_gemm_proj(const float* __restrict__ bias,
                                                   float* __restrict__ out) {
    gemm_core<1024, true>(g_aos, g_wp, out, bias);
}

// ---------------- flash attention on mma.sync (bf16x3 split) -----------------
// 128 threads / 4 warps; q-tile 64 (16 rows per warp), kv-tile 64, HD=64.
__global__ __launch_bounds__(128) void k_attn() {
    extern __shared__ char smraw[];
    const uint32_t base = (smem_u32(smraw) + 1023u) & ~1023u;
    const uint32_t QH = base, QL = base + 8192, KH = base + 16384,
                   KL = base + 24576, VH = base + 32768, VL = base + 40960;
    const int tid = threadIdx.x, lane = tid & 31, wid = tid >> 5;
    const int bh = blockIdx.y, q0 = blockIdx.x * 64;
    const size_t tok0 = (size_t)(bh >> 4) * 2048;
    const int qc = (bh & 15) * 64, kcol = 1024 + qc, vcol = 2048 + qc;

    // load Q tiles (hi/lo), SW128 swizzled
#pragma unroll
    for (int j = 0; j < 4; j++) {
        int idx = tid + j * 128;
        int r = idx >> 3, c = (idx & 7) * 8;
        size_t off = (tok0 + q0 + r) * 3072 + qc + c;
        uint32_t d = SWZ128((uint32_t)(r * 128 + c * 2));
        sts128(QH + d, *(const uint4*)(g_qkvh + off));
        sts128(QL + d, *(const uint4*)(g_qkvl + off));
    }
    __syncthreads();

    // Q fragments to registers (A-frag, 4 k16 tiles)
    uint32_t aqh[4][4], aql[4][4];
#pragma unroll
    for (int k = 0; k < 4; k++) {
        int rr = wid * 16 + (lane & 15);
        int cq = k * 16 + ((lane & 16) ? 8 : 0);
        uint32_t d = SWZ128((uint32_t)(rr * 128 + cq * 2));
        ldsm4(aqh[k][0], aqh[k][1], aqh[k][2], aqh[k][3], QH + d);
        ldsm4(aql[k][0], aql[k][1], aql[k][2], aql[k][3], QL + d);
    }

    float o[8][4];
#pragma unroll
    for (int i = 0; i < 8; i++)
#pragma unroll
        for (int j = 0; j < 4; j++) o[i][j] = 0.f;
    float m0 = -1e30f, m1 = -1e30f, l0 = 0.f, l1 = 0.f;

    for (int t = 0; t < 32; t++) {
        __syncthreads();   // previous iter's fragment reads complete
        const int kv0 = t * 64;
#pragma unroll
        for (int j = 0; j < 4; j++) {
            int idx = tid + j * 128;
            int r = idx >> 3, c = (idx & 7) * 8;
            size_t rowo = (tok0 + kv0 + r) * 3072;
            uint32_t d = SWZ128((uint32_t)(r * 128 + c * 2));
            sts128(KH + d, *(const uint4*)(g_qkvh + rowo + kcol + c));
            sts128(KL + d, *(const uint4*)(g_qkvl + rowo + kcol + c));
            sts128(VH + d, *(const uint4*)(g_qkvh + rowo + vcol + c));
            sts128(VL + d, *(const uint4*)(g_qkvl + rowo + vcol + c));
        }
        __syncthreads();

        // ---- S = Q K^T (3-term split) ----
        float s[8][4];
#pragma unroll
        for (int i = 0; i < 8; i++)
#pragma unroll
            for (int j = 0; j < 4; j++) s[i][j] = 0.f;
#pragma unroll
        for (int k = 0; k < 4; k++) {
            const int kb = k * 16 + ((lane & 8) ? 8 : 0);
#pragma unroll
            for (int p = 0; p < 4; p++) {
                const int nr = p * 16 + (lane & 7) + ((lane & 16) ? 8 : 0);
                uint32_t d = SWZ128((uint32_t)(nr * 128 + kb * 2));
                uint32_t h0, h1, h2, h3, e0, e1, e2, e3;
                ldsm4(h0, h1, h2, h3, KH + d);
                ldsm4(e0, e1, e2, e3, KL + d);
                mma16816(s[2 * p], aqh[k], h0, h1);
                mma16816(s[2 * p], aqh[k], e0, e1);
                mma16816(s[2 * p], aql[k], h0, h1);
                mma16816(s[2 * p + 1], aqh[k], h2, h3);
                mma16816(s[2 * p + 1], aqh[k], e2, e3);
                mma16816(s[2 * p + 1], aql[k], h2, h3);
            }
        }

        // ---- online softmax (rows r=lane/4 and r+8) ----
        float mx0 = -1e30f, mx1 = -1e30f;
#pragma unroll
        for (int nt = 0; nt < 8; nt++) {
#pragma unroll
            for (int j = 0; j < 4; j++) s[nt][j] *= SCALE;
            mx0 = fmaxf(mx0, fmaxf(s[nt][0], s[nt][1]));
            mx1 = fmaxf(mx1, fmaxf(s[nt][2], s[nt][3]));
        }
        mx0 = fmaxf(mx0, __shfl_xor_sync(0xffffffffu, mx0, 1));
        mx0 = fmaxf(mx0, __shfl_xor_sync(0xffffffffu, mx0, 2));
        mx1 = fmaxf(mx1, __shfl_xor_sync(0xffffffffu, mx1, 1));
        mx1 = fmaxf(mx1, __shfl_xor_sync(0xffffffffu, mx1, 2));
        const float mn0 = fmaxf(m0, mx0), mn1 = fmaxf(m1, mx1);
        const float a0 = __expf(m0 - mn0), a1 = __expf(m1 - mn1);
        m0 = mn0; m1 = mn1;
        float sum0 = 0.f, sum1 = 0.f;
#pragma unroll
        for (int nt = 0; nt < 8; nt++) {
            s[nt][0] = __expf(s[nt][0] - mn0);
            s[nt][1] = __expf(s[nt][1] - mn0);
            s[nt][2] = __expf(s[nt][2] - mn1);
            s[nt][3] = __expf(s[nt][3] - mn1);
            sum0 += s[nt][0] + s[nt][1];
            sum1 += s[nt][2] + s[nt][3];
            o[nt][0] *= a0; o[nt][1] *= a0;
            o[nt][2] *= a1; o[nt][3] *= a1;
        }
        sum0 += __shfl_xor_sync(0xffffffffu, sum0, 1);
        sum0 += __shfl_xor_sync(0xffffffffu, sum0, 2);
        sum1 += __shfl_xor_sync(0xffffffffu, sum1, 1);
        sum1 += __shfl_xor_sync(0xffffffffu, sum1, 2);
        l0 = l0 * a0 + sum0;
        l1 = l1 * a1 + sum1;

        // ---- P fragments (hi + residual lo) ----
        uint32_t ph[4][4], pl[4][4];
#pragma unroll
        for (int k = 0; k < 4; k++) {
            mkfrag(ph[k][0], pl[k][0], s[2 * k][0], s[2 * k][1]);
            mkfrag(ph[k][1], pl[k][1], s[2 * k][2], s[2 * k][3]);
            mkfrag(ph[k][2], pl[k][2], s[2 * k + 1][0], s[2 * k + 1][1]);
            mkfrag(ph[k][3], pl[k][3], s[2 * k + 1][2], s[2 * k + 1][3]);
        }

        // ---- O += P V (3-term split), V fragments via ldmatrix.trans ----
#pragma unroll
        for (int k = 0; k < 4; k++) {
            const int kvr = k * 16 + (lane & 7) + ((lane & 8) ? 8 : 0);
#pragma unroll
            for (int p = 0; p < 4; p++) {
                const int dc = p * 16 + ((lane & 16) ? 8 : 0);
                uint32_t d = SWZ128((uint32_t)(kvr * 128 + dc * 2));
                uint32_t h0, h1, h2, h3, e0, e1, e2, e3;
                ldsm4t(h0, h1, h2, h3, VH + d);
                ldsm4t(e0, e1, e2, e3, VL + d);
                mma16816(o[2 * p], ph[k], h0, h1);
                mma16816(o[2 * p], ph[k], e0, e1);
                mma16816(o[2 * p], pl[k], h0, h1);
                mma16816(o[2 * p + 1], ph[k], h2, h3);
                mma16816(o[2 * p + 1], ph[k], e2, e3);
                mma16816(o[2 * p + 1], pl[k], h2, h3);
            }
        }
    }

    // ---- normalize + write [B,N,C] (c = h*64 + d) ----
    const float inv0 = 1.f / l0, inv1 = 1.f / l1;
    const int rq = q0 + wid * 16 + (lane >> 2);
    float* dst = g_ao + (tok0 + rq) * 1024 + (bh & 15) * 64;
#pragma unroll
    for (int nt = 0; nt < 8; nt++) {
        const int col = nt * 8 + (lane & 3) * 2;
        *(float2*)&dst[col] = make_float2(o[nt][0] * inv0, o[nt][1] * inv0);
        *(float2*)&dst[col + 8 * 1024] = make_float2(o[nt][2] * inv1, o[nt][3] * inv1);
    }
}

// ---------------- launch ----------------
extern "C" void kernel_launch(void* const* d_in, const int* in_sizes, int n_in,
                              void* d_out, int out_size) {
    (void)in_sizes; (void)n_in; (void)out_size;
    const float* x      = (const float*)d_in[0];
    const float* w_qkv  = (const float*)d_in[1];
    const float* w_proj = (const float*)d_in[2];
    const float* b_proj = (const float*)d_in[3];
    float* out = (float*)d_out;

    cudaFuncSetAttribute(k_attn, cudaFuncAttributeMaxDynamicSharedMemorySize, 50176);

    k_split_x<<<16384, 256>>>(x);
    k_split_wqkv<<<6144, 256>>>(w_qkv);
    k_split_wproj<<<2048, 256>>>(w_proj);
    k_gemm_qkv<<<dim3(24, 64), 256>>>();
    k_split_qkv<<<24576, 256>>>();
    k_attn<<<dim3(32, 64), 128, 50176>>>();
    k_split_ao<<<16384, 256>>>();
    k_gemm_proj<<<dim3(8, 64), 256>>>(b_proj, out);
}

// round 4
// speedup vs baseline: 2.2722x; 1.0435x over previous
#include <cuda_runtime.h>
#include <cuda_bf16.h>
#include <cstdint>

#define SCALE 0.125f
#define SWZ128(o) ((o) ^ (((o) >> 3) & 0x70))

// ---------------- scratch (alloc-free rule: module-level device globals) ----
__device__ __nv_bfloat16 g_xs[25165824];     // 8192 x 3072  x split  [Ah|Ah|Al]
__device__ __nv_bfloat16 g_ws[9437184];      // 3072 x 3072  w_qkv split [Bh|Bl|Bh]
__device__ __nv_bfloat16 g_wp[3145728];      // 1024 x 3072  w_proj split
__device__ __nv_bfloat16 g_aos[25165824];    // 8192 x 3072  attn-out split [Ah|Ah|Al]
__device__ __nv_bfloat16 g_qkvh[25165824];   // 8192 x 3072  qkv hi bf16
__device__ __nv_bfloat16 g_qkvl[25165824];   // 8192 x 3072  qkv lo bf16

// ---------------- helpers ----------------
__device__ __forceinline__ uint32_t smem_u32(const void* p) {
    uint32_t a;
    asm("{ .reg .u64 t; cvta.to.shared.u64 t, %1; cvt.u32.u64 %0, t; }" : "=r"(a) : "l"(p));
    return a;
}
__device__ __forceinline__ void ldsm4(uint32_t& r0, uint32_t& r1, uint32_t& r2,
                                      uint32_t& r3, uint32_t a) {
    asm volatile("ldmatrix.sync.aligned.m8n8.x4.shared.b16 {%0,%1,%2,%3},[%4];"
                 : "=r"(r0), "=r"(r1), "=r"(r2), "=r"(r3) : "r"(a));
}
__device__ __forceinline__ void ldsm4t(uint32_t& r0, uint32_t& r1, uint32_t& r2,
                                       uint32_t& r3, uint32_t a) {
    asm volatile("ldmatrix.sync.aligned.m8n8.x4.trans.shared.b16 {%0,%1,%2,%3},[%4];"
                 : "=r"(r0), "=r"(r1), "=r"(r2), "=r"(r3) : "r"(a));
}
__device__ __forceinline__ void sts128(uint32_t a, uint4 v) {
    asm volatile("st.shared.v4.b32 [%0], {%1,%2,%3,%4};"
                 :: "r"(a), "r"(v.x), "r"(v.y), "r"(v.z), "r"(v.w) : "memory");
}
__device__ __forceinline__ void cpa16(uint32_t dst, const void* src) {
    asm volatile("cp.async.cg.shared.global [%0], [%1], 16;" :: "r"(dst), "l"(src)
                 : "memory");
}
#define CP_COMMIT() asm volatile("cp.async.commit_group;" ::: "memory")
#define CP_WAIT1()  asm volatile("cp.async.wait_group 1;" ::: "memory")
__device__ __forceinline__ void mma16816(float* c, const uint32_t* a,
                                         uint32_t b0, uint32_t b1) {
    asm volatile(
        "mma.sync.aligned.m16n8k16.row.col.f32.bf16.bf16.f32 "
        "{%0,%1,%2,%3},{%4,%5,%6,%7},{%8,%9},{%0,%1,%2,%3};"
        : "+f"(c[0]), "+f"(c[1]), "+f"(c[2]), "+f"(c[3])
        : "r"(a[0]), "r"(a[1]), "r"(a[2]), "r"(a[3]), "r"(b0), "r"(b1));
}
__device__ __forceinline__ uint32_t cvt2(float f0, float f1) {
    uint32_t r;
    asm("cvt.rn.bf16x2.f32 %0, %1, %2;" : "=r"(r) : "f"(f1), "f"(f0));
    return r;
}
__device__ __forceinline__ void mkfrag(uint32_t& h, uint32_t& l, float f0, float f1) {
    h = cvt2(f0, f1);
    float r0 = f0 - __uint_as_float(h << 16);
    float r1 = f1 - __uint_as_float(h & 0xffff0000u);
    l = cvt2(r0, r1);
}

// ---------------- split kernels: f32 -> [hi|hi|lo] or [hi|lo|hi] bf16 --------
__device__ __forceinline__ void split_core(const float* __restrict__ src,
                                           __nv_bfloat16* __restrict__ dst,
                                           bool bpat) {
    long i = (long)blockIdx.x * 256 + threadIdx.x;
    long r = i >> 9;
    int k2 = (int)(i & 511) << 1;
    float2 v = *(const float2*)(src + r * 1024 + k2);
    __nv_bfloat16 h0 = __float2bfloat16(v.x), h1 = __float2bfloat16(v.y);
    __nv_bfloat16 l0 = __float2bfloat16(v.x - __bfloat162float(h0));
    __nv_bfloat16 l1 = __float2bfloat16(v.y - __bfloat162float(h1));
    __nv_bfloat162 hh = __halves2bfloat162(h0, h1);
    __nv_bfloat162 ll = __halves2bfloat162(l0, l1);
    __nv_bfloat16* base = dst + r * 3072 + k2;
    *(__nv_bfloat162*)(base) = hh;
    *(__nv_bfloat162*)(base + 1024) = bpat ? ll : hh;
    *(__nv_bfloat162*)(base + 2048) = bpat ? hh : ll;
}
__global__ __launch_bounds__(256) void k_split_x(const float* __restrict__ s) {
    split_core(s, g_xs, false);
}
__global__ __launch_bounds__(256) void k_split_wqkv(const float* __restrict__ s) {
    split_core(s, g_ws, true);
}
__global__ __launch_bounds__(256) void k_split_wproj(const float* __restrict__ s) {
    split_core(s, g_wp, true);
}

// ---------------- mma.sync GEMM, cp.async 3-stage pipeline -------------------
// C[M,N] = A'[M,3072]*B'[N,3072]^T. 128x128 CTA tile, 8 warps, BK=32.
// SPLIT_OUT: write hi/lo bf16 planes (3072-wide). Else f32 +bias (NCOL wide).
template <bool SPLIT_OUT, bool HAS_BIAS, int NCOL>
__device__ __forceinline__ void gemm_core(const __nv_bfloat16* __restrict__ A,
                                          const __nv_bfloat16* __restrict__ B,
                                          float* __restrict__ C,
                                          __nv_bfloat16* __restrict__ Ch,
                                          __nv_bfloat16* __restrict__ Cl,
                                          const float* __restrict__ bias) {
    constexpr int KT = 3072;
    constexpr int STG = 10240;            // 128 rows x 80B per stage
    extern __shared__ char smraw[];
    const uint32_t smA = smem_u32(smraw);
    const uint32_t smB = smA + 3 * STG;
    const int tid = threadIdx.x, lane = tid & 31, wid = tid >> 5;
    const int wr = wid >> 2, wc = wid & 3;
    const int bm = blockIdx.y * 128, bn = blockIdx.x * 128;

    float acc[4][4][4];
#pragma unroll
    for (int i = 0; i < 4; i++)
#pragma unroll
        for (int j = 0; j < 4; j++)
#pragma unroll
            for (int q = 0; q < 4; q++) acc[i][j][q] = 0.f;

    const int lrow = tid >> 2, lc = (tid & 3) * 8;   // 2 chunks each for A and B
    const __nv_bfloat16* Ap = A + (size_t)(bm + lrow) * KT + lc;
    const __nv_bfloat16* Bp = B + (size_t)(bn + lrow) * KT + lc;
    const size_t roff = (size_t)64 * KT;

#define GEMM_LOAD(stage, it)                                                    \
    do {                                                                        \
        const int _k0 = (it) * 32;                                              \
        const uint32_t _da = smA + (stage) * STG + lrow * 80 + lc * 2;          \
        const uint32_t _db = smB + (stage) * STG + lrow * 80 + lc * 2;          \
        cpa16(_da, Ap + _k0);                                                   \
        cpa16(_da + 64 * 80, Ap + _k0 + roff);                                  \
        cpa16(_db, Bp + _k0);                                                   \
        cpa16(_db + 64 * 80, Bp + _k0 + roff);                                  \
    } while (0)

    GEMM_LOAD(0, 0); CP_COMMIT();
    GEMM_LOAD(1, 1); CP_COMMIT();

    for (int it = 0; it < 96; it++) {
        CP_WAIT1();
        __syncthreads();
        if (it + 2 < 96) GEMM_LOAD((it + 2) % 3, it + 2);
        CP_COMMIT();
        const uint32_t curA = smA + (it % 3) * STG;
        const uint32_t curB = smB + (it % 3) * STG;
#pragma unroll
        for (int k16 = 0; k16 < 2; k16++) {
            const int ka = k16 * 16 + ((lane & 16) ? 8 : 0);
            uint32_t af[4][4];
#pragma unroll
            for (int mt = 0; mt < 4; mt++) {
                const int rr = wr * 64 + mt * 16 + (lane & 15);
                ldsm4(af[mt][0], af[mt][1], af[mt][2], af[mt][3],
                      curA + rr * 80 + ka * 2);
            }
            const int kb = k16 * 16 + ((lane & 8) ? 8 : 0);
#pragma unroll
            for (int p = 0; p < 2; p++) {
                const int nr = wc * 32 + p * 16 + (lane & 7) + ((lane & 16) ? 8 : 0);
                uint32_t b0, b1, b2, b3;
                ldsm4(b0, b1, b2, b3, curB + nr * 80 + kb * 2);
#pragma unroll
                for (int mt = 0; mt < 4; mt++) {
                    mma16816(acc[mt][2 * p], af[mt], b0, b1);
                    mma16816(acc[mt][2 * p + 1], af[mt], b2, b3);
                }
            }
        }
        __syncthreads();
    }
#undef GEMM_LOAD

#pragma unroll
    for (int mt = 0; mt < 4; mt++) {
        const int row = bm + wr * 64 + mt * 16 + (lane >> 2);
#pragma unroll
        for (int nt = 0; nt < 4; nt++) {
            const int col = bn + wc * 32 + nt * 8 + (lane & 3) * 2;
            if (SPLIT_OUT) {
                uint32_t h, l;
                mkfrag(h, l, acc[mt][nt][0], acc[mt][nt][1]);
                *(uint32_t*)(Ch + (size_t)row * 3072 + col) = h;
                *(uint32_t*)(Cl + (size_t)row * 3072 + col) = l;
                mkfrag(h, l, acc[mt][nt][2], acc[mt][nt][3]);
                *(uint32_t*)(Ch + (size_t)(row + 8) * 3072 + col) = h;
                *(uint32_t*)(Cl + (size_t)(row + 8) * 3072 + col) = l;
            } else {
                float b0v = 0.f, b1v = 0.f;
                if (HAS_BIAS) { b0v = __ldg(&bias[col]); b1v = __ldg(&bias[col + 1]); }
                *(float2*)&C[(size_t)row * NCOL + col] =
                    make_float2(acc[mt][nt][0] + b0v, acc[mt][nt][1] + b1v);
                *(float2*)&C[(size_t)(row + 8) * NCOL + col] =
                    make_float2(acc[mt][nt][2] + b0v, acc[mt][nt][3] + b1v);
            }
        }
    }
}

__global__ __launch_bounds__(256) void k_gemm_qkv() {
    gemm_core<true, false, 3072>(g_xs, g_ws, nullptr, g_qkvh, g_qkvl, nullptr);
}
__global__ __launch_bounds__(256) void k_gemm_proj(const float* __restrict__ bias,
                                                   float* __restrict__ out) {
    gemm_core<false, true, 1024>(g_aos, g_wp, out, nullptr, nullptr, bias);
}

// ---------------- flash attention (bf16x3 split), cp.async 2-stage KV --------
// 128 threads / 4 warps; q-tile 64, kv-tile 64, HD=64.
__global__ __launch_bounds__(128) void k_attn() {
    extern __shared__ char smraw[];
    const uint32_t base = (smem_u32(smraw) + 1023u) & ~1023u;
    const uint32_t QH = base, QL = base + 8192;
    const uint32_t KV0 = base + 16384;               // stage s: KV0 + s*32768
    const int tid = threadIdx.x, lane = tid & 31, wid = tid >> 5;
    const int bh = blockIdx.y, q0 = blockIdx.x * 64;
    const size_t tok0 = (size_t)(bh >> 4) * 2048;
    const int qc = (bh & 15) * 64, kcol = 1024 + qc, vcol = 2048 + qc;

    // load Q tiles (hi/lo), SW128 swizzled
#pragma unroll
    for (int j = 0; j < 4; j++) {
        int idx = tid + j * 128;
        int r = idx >> 3, c = (idx & 7) * 8;
        size_t off = (tok0 + q0 + r) * 3072 + qc + c;
        uint32_t d = SWZ128((uint32_t)(r * 128 + c * 2));
        sts128(QH + d, *(const uint4*)(g_qkvh + off));
        sts128(QL + d, *(const uint4*)(g_qkvl + off));
    }

#define KV_LOAD(stage, t)                                                       \
    do {                                                                        \
        const uint32_t _kb = KV0 + (stage) * 32768;                             \
        const int _kv0 = (t) * 64;                                              \
        _Pragma("unroll")                                                       \
        for (int _j = 0; _j < 4; _j++) {                                        \
            int _idx = tid + _j * 128;                                          \
            int _r = _idx >> 3, _c = (_idx & 7) * 8;                            \
            size_t _ro = (tok0 + _kv0 + _r) * 3072;                             \
            uint32_t _d = SWZ128((uint32_t)(_r * 128 + _c * 2));                \
            cpa16(_kb + _d,         g_qkvh + _ro + kcol + _c);                  \
            cpa16(_kb + 8192 + _d,  g_qkvl + _ro + kcol + _c);                  \
            cpa16(_kb + 16384 + _d, g_qkvh + _ro + vcol + _c);                  \
            cpa16(_kb + 24576 + _d, g_qkvl + _ro + vcol + _c);                  \
        }                                                                       \
    } while (0)

    KV_LOAD(0, 0); CP_COMMIT();
    __syncthreads();

    // Q fragments to registers
    uint32_t aqh[4][4], aql[4][4];
#pragma unroll
    for (int k = 0; k < 4; k++) {
        int rr = wid * 16 + (lane & 15);
        int cq = k * 16 + ((lane & 16) ? 8 : 0);
        uint32_t d = SWZ128((uint32_t)(rr * 128 + cq * 2));
        ldsm4(aqh[k][0], aqh[k][1], aqh[k][2], aqh[k][3], QH + d);
        ldsm4(aql[k][0], aql[k][1], aql[k][2], aql[k][3], QL + d);
    }

    float o[8][4];
#pragma unroll
    for (int i = 0; i < 8; i++)
#pragma unroll
        for (int j = 0; j < 4; j++) o[i][j] = 0.f;
    float m0 = -1e30f, m1 = -1e30f, l0 = 0.f, l1 = 0.f;

    for (int t = 0; t < 32; t++) {
        if (t + 1 < 32) KV_LOAD((t + 1) & 1, t + 1);
        CP_COMMIT();
        CP_WAIT1();
        __syncthreads();
        const uint32_t KH = KV0 + (t & 1) * 32768, KL = KH + 8192,
                       VH = KH + 16384, VL = KH + 24576;

        // ---- S = Q K^T (3-term split) ----
        float s[8][4];
#pragma unroll
        for (int i = 0; i < 8; i++)
#pragma unroll
            for (int j = 0; j < 4; j++) s[i][j] = 0.f;
#pragma unroll
        for (int k = 0; k < 4; k++) {
            const int kb = k * 16 + ((lane & 8) ? 8 : 0);
#pragma unroll
            for (int p = 0; p < 4; p++) {
                const int nr = p * 16 + (lane & 7) + ((lane & 16) ? 8 : 0);
                uint32_t d = SWZ128((uint32_t)(nr * 128 + kb * 2));
                uint32_t h0, h1, h2, h3, e0, e1, e2, e3;
                ldsm4(h0, h1, h2, h3, KH + d);
                ldsm4(e0, e1, e2, e3, KL + d);
                mma16816(s[2 * p], aqh[k], h0, h1);
                mma16816(s[2 * p], aqh[k], e0, e1);
                mma16816(s[2 * p], aql[k], h0, h1);
                mma16816(s[2 * p + 1], aqh[k], h2, h3);
                mma16816(s[2 * p + 1], aqh[k], e2, e3);
                mma16816(s[2 * p + 1], aql[k], h2, h3);
            }
        }

        // ---- online softmax ----
        float mx0 = -1e30f, mx1 = -1e30f;
#pragma unroll
        for (int nt = 0; nt < 8; nt++) {
#pragma unroll
            for (int j = 0; j < 4; j++) s[nt][j] *= SCALE;
            mx0 = fmaxf(mx0, fmaxf(s[nt][0], s[nt][1]));
            mx1 = fmaxf(mx1, fmaxf(s[nt][2], s[nt][3]));
        }
        mx0 = fmaxf(mx0, __shfl_xor_sync(0xffffffffu, mx0, 1));
        mx0 = fmaxf(mx0, __shfl_xor_sync(0xffffffffu, mx0, 2));
        mx1 = fmaxf(mx1, __shfl_xor_sync(0xffffffffu, mx1, 1));
        mx1 = fmaxf(mx1, __shfl_xor_sync(0xffffffffu, mx1, 2));
        const float mn0 = fmaxf(m0, mx0), mn1 = fmaxf(m1, mx1);
        const float a0 = __expf(m0 - mn0), a1 = __expf(m1 - mn1);
        m0 = mn0; m1 = mn1;
        float sum0 = 0.f, sum1 = 0.f;
#pragma unroll
        for (int nt = 0; nt < 8; nt++) {
            s[nt][0] = __expf(s[nt][0] - mn0);
            s[nt][1] = __expf(s[nt][1] - mn0);
            s[nt][2] = __expf(s[nt][2] - mn1);
            s[nt][3] = __expf(s[nt][3] - mn1);
            sum0 += s[nt][0] + s[nt][1];
            sum1 += s[nt][2] + s[nt][3];
            o[nt][0] *= a0; o[nt][1] *= a0;
            o[nt][2] *= a1; o[nt][3] *= a1;
        }
        sum0 += __shfl_xor_sync(0xffffffffu, sum0, 1);
        sum0 += __shfl_xor_sync(0xffffffffu, sum0, 2);
        sum1 += __shfl_xor_sync(0xffffffffu, sum1, 1);
        sum1 += __shfl_xor_sync(0xffffffffu, sum1, 2);
        l0 = l0 * a0 + sum0;
        l1 = l1 * a1 + sum1;

        // ---- P fragments (hi + residual lo) ----
        uint32_t ph[4][4], pl[4][4];
#pragma unroll
        for (int k = 0; k < 4; k++) {
            mkfrag(ph[k][0], pl[k][0], s[2 * k][0], s[2 * k][1]);
            mkfrag(ph[k][1], pl[k][1], s[2 * k][2], s[2 * k][3]);
            mkfrag(ph[k][2], pl[k][2], s[2 * k + 1][0], s[2 * k + 1][1]);
            mkfrag(ph[k][3], pl[k][3], s[2 * k + 1][2], s[2 * k + 1][3]);
        }

        // ---- O += P V (3-term split) ----
#pragma unroll
        for (int k = 0; k < 4; k++) {
            const int kvr = k * 16 + (lane & 7) + ((lane & 8) ? 8 : 0);
#pragma unroll
            for (int p = 0; p < 4; p++) {
                const int dc = p * 16 + ((lane & 16) ? 8 : 0);
                uint32_t d = SWZ128((uint32_t)(kvr * 128 + dc * 2));
                uint32_t h0, h1, h2, h3, e0, e1, e2, e3;
                ldsm4t(h0, h1, h2, h3, VH + d);
                ldsm4t(e0, e1, e2, e3, VL + d);
                mma16816(o[2 * p], ph[k], h0, h1);
                mma16816(o[2 * p], ph[k], e0, e1);
                mma16816(o[2 * p], pl[k], h0, h1);
                mma16816(o[2 * p + 1], ph[k], h2, h3);
                mma16816(o[2 * p + 1], ph[k], e2, e3);
                mma16816(o[2 * p + 1], pl[k], h2, h3);
            }
        }
        __syncthreads();
    }
#undef KV_LOAD

    // ---- normalize + write split [hi|hi|lo] rows of g_aos ----
    const float inv0 = 1.f / l0, inv1 = 1.f / l1;
    const int rq = q0 + wid * 16 + (lane >> 2);
    __nv_bfloat16* d0 = g_aos + (tok0 + rq) * 3072 + (bh & 15) * 64;
    __nv_bfloat16* d1 = d0 + 8 * 3072;
#pragma unroll
    for (int nt = 0; nt < 8; nt++) {
        const int col = nt * 8 + (lane & 3) * 2;
        uint32_t h, l;
        mkfrag(h, l, o[nt][0] * inv0, o[nt][1] * inv0);
        *(uint32_t*)(d0 + col) = h;
        *(uint32_t*)(d0 + 1024 + col) = h;
        *(uint32_t*)(d0 + 2048 + col) = l;
        mkfrag(h, l, o[nt][2] * inv1, o[nt][3] * inv1);
        *(uint32_t*)(d1 + col) = h;
        *(uint32_t*)(d1 + 1024 + col) = h;
        *(uint32_t*)(d1 + 2048 + col) = l;
    }
}

// ---------------- launch ----------------
extern "C" void kernel_launch(void* const* d_in, const int* in_sizes, int n_in,
                              void* d_out, int out_size) {
    (void)in_sizes; (void)n_in; (void)out_size;
    const float* x      = (const float*)d_in[0];
    const float* w_qkv  = (const float*)d_in[1];
    const float* w_proj = (const float*)d_in[2];
    const float* b_proj = (const float*)d_in[3];
    float* out = (float*)d_out;

    static bool attr_set = false;
    if (!attr_set) {
        cudaFuncSetAttribute(k_gemm_qkv, cudaFuncAttributeMaxDynamicSharedMemorySize, 61440);
        cudaFuncSetAttribute(k_gemm_proj, cudaFuncAttributeMaxDynamicSharedMemorySize, 61440);
        cudaFuncSetAttribute(k_attn, cudaFuncAttributeMaxDynamicSharedMemorySize, 83968);
        attr_set = true;
    }

    k_split_x<<<16384, 256>>>(x);
    k_split_wqkv<<<6144, 256>>>(w_qkv);
    k_split_wproj<<<2048, 256>>>(w_proj);
    k_gemm_qkv<<<dim3(24, 64), 256, 61440>>>();
    k_attn<<<dim3(32, 64), 128, 83968>>>();
    k_gemm_proj<<<dim3(8, 64), 256, 61440>>>(b_proj, out);
}

// round 5
// speedup vs baseline: 2.4884x; 1.0951x over previous
#include <cuda_runtime.h>
#include <cuda_bf16.h>
#include <cstdint>

#define SCALE 0.125f
#define LOG2E 1.4426950408889634f
#define SWZ128(o) ((o) ^ (((o) >> 3) & 0x70))

// ---------------- scratch (alloc-free rule: module-level device globals) ----
__device__ __nv_bfloat16 g_xs[25165824];     // 8192 x 3072  x split  [Ah|Ah|Al]
__device__ __nv_bfloat16 g_ws[9437184];      // 3072 x 3072  w_qkv split [Bh|Bl|Bh]
__device__ __nv_bfloat16 g_wp[3145728];      // 1024 x 3072  w_proj split
__device__ __nv_bfloat16 g_aos[25165824];    // 8192 x 3072  attn-out split [Ah|Ah|Al]
__device__ __nv_bfloat16 g_qkvh[25165824];   // 8192 x 3072  qkv hi bf16
__device__ __nv_bfloat16 g_qkvl[25165824];   // 8192 x 3072  qkv lo bf16

// ---------------- helpers ----------------
__device__ __forceinline__ uint32_t smem_u32(const void* p) {
    uint32_t a;
    asm("{ .reg .u64 t; cvta.to.shared.u64 t, %1; cvt.u32.u64 %0, t; }" : "=r"(a) : "l"(p));
    return a;
}
__device__ __forceinline__ void ldsm4(uint32_t& r0, uint32_t& r1, uint32_t& r2,
                                      uint32_t& r3, uint32_t a) {
    asm volatile("ldmatrix.sync.aligned.m8n8.x4.shared.b16 {%0,%1,%2,%3},[%4];"
                 : "=r"(r0), "=r"(r1), "=r"(r2), "=r"(r3) : "r"(a));
}
__device__ __forceinline__ void ldsm4t(uint32_t& r0, uint32_t& r1, uint32_t& r2,
                                       uint32_t& r3, uint32_t a) {
    asm volatile("ldmatrix.sync.aligned.m8n8.x4.trans.shared.b16 {%0,%1,%2,%3},[%4];"
                 : "=r"(r0), "=r"(r1), "=r"(r2), "=r"(r3) : "r"(a));
}
__device__ __forceinline__ void sts128(uint32_t a, uint4 v) {
    asm volatile("st.shared.v4.b32 [%0], {%1,%2,%3,%4};"
                 :: "r"(a), "r"(v.x), "r"(v.y), "r"(v.z), "r"(v.w) : "memory");
}
__device__ __forceinline__ void cpa16(uint32_t dst, const void* src) {
    asm volatile("cp.async.cg.shared.global [%0], [%1], 16;" :: "r"(dst), "l"(src)
                 : "memory");
}
#define CP_COMMIT() asm volatile("cp.async.commit_group;" ::: "memory")
#define CP_WAIT1()  asm volatile("cp.async.wait_group 1;" ::: "memory")
#define CP_WAIT0()  asm volatile("cp.async.wait_group 0;" ::: "memory")
__device__ __forceinline__ void mma16816(float* c, const uint32_t* a,
                                         uint32_t b0, uint32_t b1) {
    asm volatile(
        "mma.sync.aligned.m16n8k16.row.col.f32.bf16.bf16.f32 "
        "{%0,%1,%2,%3},{%4,%5,%6,%7},{%8,%9},{%0,%1,%2,%3};"
        : "+f"(c[0]), "+f"(c[1]), "+f"(c[2]), "+f"(c[3])
        : "r"(a[0]), "r"(a[1]), "r"(a[2]), "r"(a[3]), "r"(b0), "r"(b1));
}
__device__ __forceinline__ uint32_t cvt2(float f0, float f1) {
    uint32_t r;
    asm("cvt.rn.bf16x2.f32 %0, %1, %2;" : "=r"(r) : "f"(f1), "f"(f0));
    return r;
}
__device__ __forceinline__ void mkfrag(uint32_t& h, uint32_t& l, float f0, float f1) {
    h = cvt2(f0, f1);
    float r0 = f0 - __uint_as_float(h << 16);
    float r1 = f1 - __uint_as_float(h & 0xffff0000u);
    l = cvt2(r0, r1);
}

// ---------------- split kernels: f32 -> [hi|hi|lo] or [hi|lo|hi] bf16 --------
__device__ __forceinline__ void split_core(const float* __restrict__ src,
                                           __nv_bfloat16* __restrict__ dst,
                                           bool bpat) {
    long i = (long)blockIdx.x * 256 + threadIdx.x;
    long r = i >> 9;
    int k2 = (int)(i & 511) << 1;
    float2 v = *(const float2*)(src + r * 1024 + k2);
    __nv_bfloat16 h0 = __float2bfloat16(v.x), h1 = __float2bfloat16(v.y);
    __nv_bfloat16 l0 = __float2bfloat16(v.x - __bfloat162float(h0));
    __nv_bfloat16 l1 = __float2bfloat16(v.y - __bfloat162float(h1));
    __nv_bfloat162 hh = __halves2bfloat162(h0, h1);
    __nv_bfloat162 ll = __halves2bfloat162(l0, l1);
    __nv_bfloat16* base = dst + r * 3072 + k2;
    *(__nv_bfloat162*)(base) = hh;
    *(__nv_bfloat162*)(base + 1024) = bpat ? ll : hh;
    *(__nv_bfloat162*)(base + 2048) = bpat ? hh : ll;
}
__global__ __launch_bounds__(256) void k_split_x(const float* __restrict__ s) {
    split_core(s, g_xs, false);
}
__global__ __launch_bounds__(256) void k_split_wqkv(const float* __restrict__ s) {
    split_core(s, g_ws, true);
}
__global__ __launch_bounds__(256) void k_split_wproj(const float* __restrict__ s) {
    split_core(s, g_wp, true);
}

// ---------------- mma.sync GEMM, cp.async 3-stage, 1 sync/iter ---------------
// C[M,N] = A'[M,3072]*B'[N,3072]^T. 128x128 CTA tile, 8 warps, BK=32.
template <bool SPLIT_OUT, bool HAS_BIAS, int NCOL>
__device__ __forceinline__ void gemm_core(const __nv_bfloat16* __restrict__ A,
                                          const __nv_bfloat16* __restrict__ B,
                                          float* __restrict__ C,
                                          __nv_bfloat16* __restrict__ Ch,
                                          __nv_bfloat16* __restrict__ Cl,
                                          const float* __restrict__ bias) {
    constexpr int KT = 3072;
    constexpr int STG = 10240;            // 128 rows x 80B per stage
    extern __shared__ char smraw[];
    const uint32_t smA = smem_u32(smraw);
    const uint32_t smB = smA + 3 * STG;
    const int tid = threadIdx.x, lane = tid & 31, wid = tid >> 5;
    const int wr = wid >> 2, wc = wid & 3;
    const int bm = blockIdx.y * 128, bn = blockIdx.x * 128;

    float acc[4][4][4];
#pragma unroll
    for (int i = 0; i < 4; i++)
#pragma unroll
        for (int j = 0; j < 4; j++)
#pragma unroll
            for (int q = 0; q < 4; q++) acc[i][j][q] = 0.f;

    const int lrow = tid >> 2, lc = (tid & 3) * 8;
    const __nv_bfloat16* Ap = A + (size_t)(bm + lrow) * KT + lc;
    const __nv_bfloat16* Bp = B + (size_t)(bn + lrow) * KT + lc;
    const size_t roff = (size_t)64 * KT;

#define GEMM_LOAD(stage, it)                                                    \
    do {                                                                        \
        const int _k0 = (it) * 32;                                              \
        const uint32_t _da = smA + (stage) * STG + lrow * 80 + lc * 2;          \
        const uint32_t _db = smB + (stage) * STG + lrow * 80 + lc * 2;          \
        cpa16(_da, Ap + _k0);                                                   \
        cpa16(_da + 64 * 80, Ap + _k0 + roff);                                  \
        cpa16(_db, Bp + _k0);                                                   \
        cpa16(_db + 64 * 80, Bp + _k0 + roff);                                  \
    } while (0)

    GEMM_LOAD(0, 0); CP_COMMIT();
    GEMM_LOAD(1, 1); CP_COMMIT();

    // per-warp fragment base offsets
    const int arow = wr * 64 + (lane & 15);
    const int aoff = (lane & 16) ? 8 : 0;          // k-offset within k16 for A
    const int brow = wc * 32 + (lane & 7) + ((lane & 16) ? 8 : 0);
    const int boff = (lane & 8) ? 8 : 0;

    for (int it = 0; it < 96; it++) {
        CP_WAIT1();
        __syncthreads();                 // iter it-1 reads done; stage it ready
        if (it + 2 < 96) GEMM_LOAD((it + 2) % 3, it + 2);
        CP_COMMIT();
        const uint32_t curA = smA + (it % 3) * STG;
        const uint32_t curB = smB + (it % 3) * STG;

        // hoist all A fragments (both k16 halves)
        uint32_t af[2][4][4];
#pragma unroll
        for (int k16 = 0; k16 < 2; k16++) {
            const int ka = k16 * 16 + aoff;
#pragma unroll
            for (int mt = 0; mt < 4; mt++)
                ldsm4(af[k16][mt][0], af[k16][mt][1], af[k16][mt][2],
                      af[k16][mt][3], curA + (arow + mt * 16) * 80 + ka * 2);
        }
        // B fragments double-buffered: prefetch next while 8-MMA burst runs
        uint32_t bf[2][4];
#define LDB(c, buf)                                                             \
        ldsm4(bf[buf][0], bf[buf][1], bf[buf][2], bf[buf][3],                   \
              curB + (brow + ((c) & 1) * 16) * 80 + (((c) >> 1) * 16 + boff) * 2)
        LDB(0, 0);
#pragma unroll
        for (int c = 0; c < 4; c++) {
            const int cur = c & 1;
            if (c < 3) LDB(c + 1, cur ^ 1);
            const int k16 = c >> 1, p = c & 1;
#pragma unroll
            for (int mt = 0; mt < 4; mt++) {
                mma16816(acc[mt][2 * p], af[k16][mt], bf[cur][0], bf[cur][1]);
                mma16816(acc[mt][2 * p + 1], af[k16][mt], bf[cur][2], bf[cur][3]);
            }
        }
#undef LDB
    }
#undef GEMM_LOAD

#pragma unroll
    for (int mt = 0; mt < 4; mt++) {
        const int row = bm + wr * 64 + mt * 16 + (lane >> 2);
#pragma unroll
        for (int nt = 0; nt < 4; nt++) {
            const int col = bn + wc * 32 + nt * 8 + (lane & 3) * 2;
            if (SPLIT_OUT) {
                uint32_t h, l;
                mkfrag(h, l, acc[mt][nt][0], acc[mt][nt][1]);
                *(uint32_t*)(Ch + (size_t)row * 3072 + col) = h;
                *(uint32_t*)(Cl + (size_t)row * 3072 + col) = l;
                mkfrag(h, l, acc[mt][nt][2], acc[mt][nt][3]);
                *(uint32_t*)(Ch + (size_t)(row + 8) * 3072 + col) = h;
                *(uint32_t*)(Cl + (size_t)(row + 8) * 3072 + col) = l;
            } else {
                float b0v = 0.f, b1v = 0.f;
                if (HAS_BIAS) { b0v = __ldg(&bias[col]); b1v = __ldg(&bias[col + 1]); }
                *(float2*)&C[(size_t)row * NCOL + col] =
                    make_float2(acc[mt][nt][0] + b0v, acc[mt][nt][1] + b1v);
                *(float2*)&C[(size_t)(row + 8) * NCOL + col] =
                    make_float2(acc[mt][nt][2] + b0v, acc[mt][nt][3] + b1v);
            }
        }
    }
}

__global__ __launch_bounds__(256, 2) void k_gemm_qkv() {
    gemm_core<true, false, 3072>(g_xs, g_ws, nullptr, g_qkvh, g_qkvl, nullptr);
}
__global__ __launch_bounds__(256, 2) void k_gemm_proj(const float* __restrict__ bias,
                                                      float* __restrict__ out) {
    gemm_core<false, true, 1024>(g_aos, g_wp, out, nullptr, nullptr, bias);
}

// ---------------- flash attention (bf16x3 split), 1 sync/iter ----------------
// 128 threads / 4 warps; q-tile 64, kv-tile 64, HD=64. exp2-domain softmax.
__global__ __launch_bounds__(128) void k_attn() {
    extern __shared__ char smraw[];
    const uint32_t base = (smem_u32(smraw) + 1023u) & ~1023u;
    const uint32_t QH = base, QL = base + 8192;
    const uint32_t KV0 = base + 16384;               // stage s: KV0 + s*32768
    const int tid = threadIdx.x, lane = tid & 31, wid = tid >> 5;
    const int bh = blockIdx.y, q0 = blockIdx.x * 64;
    const size_t tok0 = (size_t)(bh >> 4) * 2048;
    const int qc = (bh & 15) * 64, kcol = 1024 + qc, vcol = 2048 + qc;
    constexpr float CS = SCALE * LOG2E;

    // load Q tiles (hi/lo), SW128 swizzled
#pragma unroll
    for (int j = 0; j < 4; j++) {
        int idx = tid + j * 128;
        int r = idx >> 3, c = (idx & 7) * 8;
        size_t off = (tok0 + q0 + r) * 3072 + qc + c;
        uint32_t d = SWZ128((uint32_t)(r * 128 + c * 2));
        sts128(QH + d, *(const uint4*)(g_qkvh + off));
        sts128(QL + d, *(const uint4*)(g_qkvl + off));
    }

#define KV_LOAD(stage, t)                                                       \
    do {                                                                        \
        const uint32_t _kb = KV0 + (stage) * 32768;                             \
        const int _kv0 = (t) * 64;                                              \
        _Pragma("unroll")                                                       \
        for (int _j = 0; _j < 4; _j++) {                                        \
            int _idx = tid + _j * 128;                                          \
            int _r = _idx >> 3, _c = (_idx & 7) * 8;                            \
            size_t _ro = (tok0 + _kv0 + _r) * 3072;                             \
            uint32_t _d = SWZ128((uint32_t)(_r * 128 + _c * 2));                \
            cpa16(_kb + _d,         g_qkvh + _ro + kcol + _c);                  \
            cpa16(_kb + 8192 + _d,  g_qkvl + _ro + kcol + _c);                  \
            cpa16(_kb + 16384 + _d, g_qkvh + _ro + vcol + _c);                  \
            cpa16(_kb + 24576 + _d, g_qkvl + _ro + vcol + _c);                  \
        }                                                                       \
    } while (0)

    KV_LOAD(0, 0); CP_COMMIT();
    __syncthreads();

    // Q fragments to registers
    uint32_t aqh[4][4], aql[4][4];
#pragma unroll
    for (int k = 0; k < 4; k++) {
        int rr = wid * 16 + (lane & 15);
        int cq = k * 16 + ((lane & 16) ? 8 : 0);
        uint32_t d = SWZ128((uint32_t)(rr * 128 + cq * 2));
        ldsm4(aqh[k][0], aqh[k][1], aqh[k][2], aqh[k][3], QH + d);
        ldsm4(aql[k][0], aql[k][1], aql[k][2], aql[k][3], QL + d);
    }

    float o[8][4];
#pragma unroll
    for (int i = 0; i < 8; i++)
#pragma unroll
        for (int j = 0; j < 4; j++) o[i][j] = 0.f;
    float m0 = -1e30f, m1 = -1e30f, l0 = 0.f, l1 = 0.f;

    for (int t = 0; t < 32; t++) {
        CP_WAIT0();
        __syncthreads();                 // iter t-1 reads done; stage t ready
        if (t + 1 < 32) { KV_LOAD((t + 1) & 1, t + 1); CP_COMMIT(); }
        const uint32_t KH = KV0 + (t & 1) * 32768, KL = KH + 8192,
                       VH = KH + 16384, VL = KH + 24576;

        // ---- S = Q K^T (3-term split) ----
        float s[8][4];
#pragma unroll
        for (int i = 0; i < 8; i++)
#pragma unroll
            for (int j = 0; j < 4; j++) s[i][j] = 0.f;
#pragma unroll
        for (int k = 0; k < 4; k++) {
            const int kb = k * 16 + ((lane & 8) ? 8 : 0);
#pragma unroll
            for (int p = 0; p < 4; p++) {
                const int nr = p * 16 + (lane & 7) + ((lane & 16) ? 8 : 0);
                uint32_t d = SWZ128((uint32_t)(nr * 128 + kb * 2));
                uint32_t h0, h1, h2, h3, e0, e1, e2, e3;
                ldsm4(h0, h1, h2, h3, KH + d);
                ldsm4(e0, e1, e2, e3, KL + d);
                mma16816(s[2 * p], aqh[k], h0, h1);
                mma16816(s[2 * p], aqh[k], e0, e1);
                mma16816(s[2 * p], aql[k], h0, h1);
                mma16816(s[2 * p + 1], aqh[k], h2, h3);
                mma16816(s[2 * p + 1], aqh[k], e2, e3);
                mma16816(s[2 * p + 1], aql[k], h2, h3);
            }
        }

        // ---- online softmax in exp2 domain (z = s*SCALE*log2e) ----
        float mx0 = -1e30f, mx1 = -1e30f;
#pragma unroll
        for (int nt = 0; nt < 8; nt++) {
#pragma unroll
            for (int j = 0; j < 4; j++) s[nt][j] *= CS;
            mx0 = fmaxf(mx0, fmaxf(s[nt][0], s[nt][1]));
            mx1 = fmaxf(mx1, fmaxf(s[nt][2], s[nt][3]));
        }
        mx0 = fmaxf(mx0, __shfl_xor_sync(0xffffffffu, mx0, 1));
        mx0 = fmaxf(mx0, __shfl_xor_sync(0xffffffffu, mx0, 2));
        mx1 = fmaxf(mx1, __shfl_xor_sync(0xffffffffu, mx1, 1));
        mx1 = fmaxf(mx1, __shfl_xor_sync(0xffffffffu, mx1, 2));
        const float mn0 = fmaxf(m0, mx0), mn1 = fmaxf(m1, mx1);
        const float a0 = exp2f(m0 - mn0), a1 = exp2f(m1 - mn1);
        m0 = mn0; m1 = mn1;
        float sum0 = 0.f, sum1 = 0.f;
#pragma unroll
        for (int nt = 0; nt < 8; nt++) {
            s[nt][0] = exp2f(s[nt][0] - mn0);
            s[nt][1] = exp2f(s[nt][1] - mn0);
            s[nt][2] = exp2f(s[nt][2] - mn1);
            s[nt][3] = exp2f(s[nt][3] - mn1);
            sum0 += s[nt][0] + s[nt][1];
            sum1 += s[nt][2] + s[nt][3];
            o[nt][0] *= a0; o[nt][1] *= a0;
            o[nt][2] *= a1; o[nt][3] *= a1;
        }
        sum0 += __shfl_xor_sync(0xffffffffu, sum0, 1);
        sum0 += __shfl_xor_sync(0xffffffffu, sum0, 2);
        sum1 += __shfl_xor_sync(0xffffffffu, sum1, 1);
        sum1 += __shfl_xor_sync(0xffffffffu, sum1, 2);
        l0 = l0 * a0 + sum0;
        l1 = l1 * a1 + sum1;

        // ---- P fragments (hi + residual lo) ----
        uint32_t ph[4][4], pl[4][4];
#pragma unroll
        for (int k = 0; k < 4; k++) {
            mkfrag(ph[k][0], pl[k][0], s[2 * k][0], s[2 * k][1]);
            mkfrag(ph[k][1], pl[k][1], s[2 * k][2], s[2 * k][3]);
            mkfrag(ph[k][2], pl[k][2], s[2 * k + 1][0], s[2 * k + 1][1]);
            mkfrag(ph[k][3], pl[k][3], s[2 * k + 1][2], s[2 * k + 1][3]);
        }

        // ---- O += P V (3-term split) ----
#pragma unroll
        for (int k = 0; k < 4; k++) {
            const int kvr = k * 16 + (lane & 7) + ((lane & 8) ? 8 : 0);
#pragma unroll
            for (int p = 0; p < 4; p++) {
                const int dc = p * 16 + ((lane & 16) ? 8 : 0);
                uint32_t d = SWZ128((uint32_t)(kvr * 128 + dc * 2));
                uint32_t h0, h1, h2, h3, e0, e1, e2, e3;
                ldsm4t(h0, h1, h2, h3, VH + d);
                ldsm4t(e0, e1, e2, e3, VL + d);
                mma16816(o[2 * p], ph[k], h0, h1);
                mma16816(o[2 * p], ph[k], e0, e1);
                mma16816(o[2 * p], pl[k], h0, h1);
                mma16816(o[2 * p + 1], ph[k], h2, h3);
                mma16816(o[2 * p + 1], ph[k], e2, e3);
                mma16816(o[2 * p + 1], pl[k], h2, h3);
            }
        }
    }
#undef KV_LOAD

    // ---- normalize + write split [hi|hi|lo] rows of g_aos ----
    const float inv0 = 1.f / l0, inv1 = 1.f / l1;
    const int rq = q0 + wid * 16 + (lane >> 2);
    __nv_bfloat16* d0 = g_aos + (tok0 + rq) * 3072 + (bh & 15) * 64;
    __nv_bfloat16* d1 = d0 + 8 * 3072;
#pragma unroll
    for (int nt = 0; nt < 8; nt++) {
        const int col = nt * 8 + (lane & 3) * 2;
        uint32_t h, l;
        mkfrag(h, l, o[nt][0] * inv0, o[nt][1] * inv0);
        *(uint32_t*)(d0 + col) = h;
        *(uint32_t*)(d0 + 1024 + col) = h;
        *(uint32_t*)(d0 + 2048 + col) = l;
        mkfrag(h, l, o[nt][2] * inv1, o[nt][3] * inv1);
        *(uint32_t*)(d1 + col) = h;
        *(uint32_t*)(d1 + 1024 + col) = h;
        *(uint32_t*)(d1 + 2048 + col) = l;
    }
}

// ---------------- launch ----------------
extern "C" void kernel_launch(void* const* d_in, const int* in_sizes, int n_in,
                              void* d_out, int out_size) {
    (void)in_sizes; (void)n_in; (void)out_size;
    const float* x      = (const float*)d_in[0];
    const float* w_qkv  = (const float*)d_in[1];
    const float* w_proj = (const float*)d_in[2];
    const float* b_proj = (const float*)d_in[3];
    float* out = (float*)d_out;

    static bool attr_set = false;
    if (!attr_set) {
        cudaFuncSetAttribute(k_gemm_qkv, cudaFuncAttributeMaxDynamicSharedMemorySize, 61440);
        cudaFuncSetAttribute(k_gemm_proj, cudaFuncAttributeMaxDynamicSharedMemorySize, 61440);
        cudaFuncSetAttribute(k_attn, cudaFuncAttributeMaxDynamicSharedMemorySize, 83968);
        attr_set = true;
    }

    k_split_x<<<16384, 256>>>(x);
    k_split_wqkv<<<6144, 256>>>(w_qkv);
    k_split_wproj<<<2048, 256>>>(w_proj);
    k_gemm_qkv<<<dim3(24, 64), 256, 61440>>>();
    k_attn<<<dim3(32, 64), 128, 83968>>>();
    k_gemm_proj<<<dim3(8, 64), 256, 61440>>>(b_proj, out);
}

// round 6
// speedup vs baseline: 3.0038x; 1.2071x over previous
#include <cuda_runtime.h>
#include <cuda_bf16.h>
#include <cstdint>

#define SCALE 0.125f
#define LOG2E 1.4426950408889634f
#define SWZ128(o) ((o) ^ (((o) >> 3) & 0x70))

// ---------------- scratch (alloc-free rule: module-level device globals) ----
__device__ __nv_bfloat16 g_xs[25165824];     // 8192 x 3072  x split  [Ah|Ah|Al]
__device__ __nv_bfloat16 g_ws[9437184];      // 3072 x 3072  w_qkv split [Bh|Bl|Bh]
__device__ __nv_bfloat16 g_wp[3145728];      // 1024 x 3072  w_proj split
__device__ __nv_bfloat16 g_aos[25165824];    // 8192 x 3072  attn-out split [Ah|Ah|Al]
__device__ __nv_bfloat16 g_qkvh[25165824];   // 8192 x 3072  qkv hi bf16
__device__ __nv_bfloat16 g_qkvl[25165824];   // 8192 x 3072  qkv lo bf16

// ---------------- helpers ----------------
__device__ __forceinline__ uint32_t smem_u32(const void* p) {
    uint32_t a;
    asm("{ .reg .u64 t; cvta.to.shared.u64 t, %1; cvt.u32.u64 %0, t; }" : "=r"(a) : "l"(p));
    return a;
}
__device__ __forceinline__ void ldsm4(uint32_t& r0, uint32_t& r1, uint32_t& r2,
                                      uint32_t& r3, uint32_t a) {
    asm volatile("ldmatrix.sync.aligned.m8n8.x4.shared.b16 {%0,%1,%2,%3},[%4];"
                 : "=r"(r0), "=r"(r1), "=r"(r2), "=r"(r3) : "r"(a));
}
__device__ __forceinline__ void ldsm4t(uint32_t& r0, uint32_t& r1, uint32_t& r2,
                                       uint32_t& r3, uint32_t a) {
    asm volatile("ldmatrix.sync.aligned.m8n8.x4.trans.shared.b16 {%0,%1,%2,%3},[%4];"
                 : "=r"(r0), "=r"(r1), "=r"(r2), "=r"(r3) : "r"(a));
}
__device__ __forceinline__ void sts128(uint32_t a, uint4 v) {
    asm volatile("st.shared.v4.b32 [%0], {%1,%2,%3,%4};"
                 :: "r"(a), "r"(v.x), "r"(v.y), "r"(v.z), "r"(v.w) : "memory");
}
__device__ __forceinline__ void cpa16(uint32_t dst, const void* src) {
    asm volatile("cp.async.cg.shared.global [%0], [%1], 16;" :: "r"(dst), "l"(src)
                 : "memory");
}
#define CP_COMMIT() asm volatile("cp.async.commit_group;" ::: "memory")
#define CP_WAIT0()  asm volatile("cp.async.wait_group 0;" ::: "memory")
__device__ __forceinline__ void mma16816(float* c, const uint32_t* a,
                                         uint32_t b0, uint32_t b1) {
    asm volatile(
        "mma.sync.aligned.m16n8k16.row.col.f32.bf16.bf16.f32 "
        "{%0,%1,%2,%3},{%4,%5,%6,%7},{%8,%9},{%0,%1,%2,%3};"
        : "+f"(c[0]), "+f"(c[1]), "+f"(c[2]), "+f"(c[3])
        : "r"(a[0]), "r"(a[1]), "r"(a[2]), "r"(a[3]), "r"(b0), "r"(b1));
}
__device__ __forceinline__ uint32_t cvt2(float f0, float f1) {
    uint32_t r;
    asm("cvt.rn.bf16x2.f32 %0, %1, %2;" : "=r"(r) : "f"(f1), "f"(f0));
    return r;
}
__device__ __forceinline__ void mkfrag(uint32_t& h, uint32_t& l, float f0, float f1) {
    h = cvt2(f0, f1);
    float r0 = f0 - __uint_as_float(h << 16);
    float r1 = f1 - __uint_as_float(h & 0xffff0000u);
    l = cvt2(r0, r1);
}

// ---------------- split kernels: f32 -> [hi|hi|lo] or [hi|lo|hi] bf16 --------
__device__ __forceinline__ void split_core(const float* __restrict__ src,
                                           __nv_bfloat16* __restrict__ dst,
                                           bool bpat) {
    long i = (long)blockIdx.x * 256 + threadIdx.x;
    long r = i >> 9;
    int k2 = (int)(i & 511) << 1;
    float2 v = *(const float2*)(src + r * 1024 + k2);
    __nv_bfloat16 h0 = __float2bfloat16(v.x), h1 = __float2bfloat16(v.y);
    __nv_bfloat16 l0 = __float2bfloat16(v.x - __bfloat162float(h0));
    __nv_bfloat16 l1 = __float2bfloat16(v.y - __bfloat162float(h1));
    __nv_bfloat162 hh = __halves2bfloat162(h0, h1);
    __nv_bfloat162 ll = __halves2bfloat162(l0, l1);
    __nv_bfloat16* base = dst + r * 3072 + k2;
    *(__nv_bfloat162*)(base) = hh;
    *(__nv_bfloat162*)(base + 1024) = bpat ? ll : hh;
    *(__nv_bfloat162*)(base + 2048) = bpat ? hh : ll;
}
__global__ __launch_bounds__(256) void k_split_x(const float* __restrict__ s) {
    split_core(s, g_xs, false);
}
__global__ __launch_bounds__(256) void k_split_wqkv(const float* __restrict__ s) {
    split_core(s, g_ws, true);
}
__global__ __launch_bounds__(256) void k_split_wproj(const float* __restrict__ s) {
    split_core(s, g_wp, true);
}

// ---------------- mma.sync GEMM, BK=64, 2-stage, 1 sync/iter -----------------
// C[M,N] = A'[M,3072]*B'[N,3072]^T. 128x128 CTA tile, 8 warps, SW128 smem.
template <bool SPLIT_OUT, bool HAS_BIAS, int NCOL>
__device__ __forceinline__ void gemm_core(const __nv_bfloat16* __restrict__ A,
                                          const __nv_bfloat16* __restrict__ B,
                                          float* __restrict__ C,
                                          __nv_bfloat16* __restrict__ Ch,
                                          __nv_bfloat16* __restrict__ Cl,
                                          const float* __restrict__ bias) {
    constexpr int KT = 3072;
    constexpr int STG = 32768;           // per stage: A 16K + B 16K
    extern __shared__ char smraw[];
    const uint32_t base = (smem_u32(smraw) + 1023u) & ~1023u;
    const int tid = threadIdx.x, lane = tid & 31, wid = tid >> 5;
    const int wr = wid >> 2, wc = wid & 3;
    const int bm = blockIdx.y * 128, bn = blockIdx.x * 128;

    float acc[4][4][4];
#pragma unroll
    for (int i = 0; i < 4; i++)
#pragma unroll
        for (int j = 0; j < 4; j++)
#pragma unroll
            for (int q = 0; q < 4; q++) acc[i][j][q] = 0.f;

    const int lr = tid >> 3, lc8 = tid & 7;     // row 0..31 (+j*32), 16B chunk
    const __nv_bfloat16* Ap = A + (size_t)(bm + lr) * KT + lc8 * 8;
    const __nv_bfloat16* Bp = B + (size_t)(bn + lr) * KT + lc8 * 8;

#define GEMM_LOAD(stage, it)                                                    \
    do {                                                                        \
        const int _k0 = (it) * 64;                                              \
        const uint32_t _sa = base + (stage) * STG;                              \
        const uint32_t _sb = _sa + 16384;                                       \
        _Pragma("unroll")                                                       \
        for (int _j = 0; _j < 4; _j++) {                                        \
            const uint32_t _d = SWZ128((uint32_t)((lr + _j * 32) * 128 + lc8 * 16)); \
            cpa16(_sa + _d, Ap + (size_t)_j * 32 * KT + _k0);                   \
            cpa16(_sb + _d, Bp + (size_t)_j * 32 * KT + _k0);                   \
        }                                                                       \
    } while (0)

    GEMM_LOAD(0, 0); CP_COMMIT();

    const int arow = wr * 64 + (lane & 15);
    const int aoff = (lane & 16) ? 8 : 0;
    const int brow = wc * 32 + (lane & 7) + ((lane & 16) ? 8 : 0);
    const int boff = (lane & 8) ? 8 : 0;

    for (int it = 0; it < 48; it++) {
        CP_WAIT0();
        __syncthreads();
        if (it + 1 < 48) { GEMM_LOAD((it + 1) & 1, it + 1); CP_COMMIT(); }
        const uint32_t curA = base + (it & 1) * STG;
        const uint32_t curB = curA + 16384;

        uint32_t af[2][4][4], bf[2][4];
#define LDA(k16, buf)                                                           \
        _Pragma("unroll")                                                       \
        for (int _mt = 0; _mt < 4; _mt++)                                       \
            ldsm4(af[buf][_mt][0], af[buf][_mt][1], af[buf][_mt][2],            \
                  af[buf][_mt][3],                                              \
                  curA + SWZ128((uint32_t)((arow + _mt * 16) * 128 +            \
                                           ((k16) * 16 + aoff) * 2)))
#define LDB(k16, p, buf)                                                        \
        ldsm4(bf[buf][0], bf[buf][1], bf[buf][2], bf[buf][3],                   \
              curB + SWZ128((uint32_t)((brow + (p) * 16) * 128 +                \
                                       ((k16) * 16 + boff) * 2)))
        LDA(0, 0);
        LDB(0, 0, 0);
#pragma unroll
        for (int c8 = 0; c8 < 8; c8++) {
            const int k16 = c8 >> 1, p = c8 & 1;
            const int ba = k16 & 1, bb = c8 & 1;
            if (c8 < 7) LDB((c8 + 1) >> 1, (c8 + 1) & 1, bb ^ 1);
            if (p == 0 && k16 < 3) LDA(k16 + 1, ba ^ 1);
#pragma unroll
            for (int mt = 0; mt < 4; mt++) {
                mma16816(acc[mt][2 * p], af[ba][mt], bf[bb][0], bf[bb][1]);
                mma16816(acc[mt][2 * p + 1], af[ba][mt], bf[bb][2], bf[bb][3]);
            }
        }
#undef LDA
#undef LDB
    }
#undef GEMM_LOAD

#pragma unroll
    for (int mt = 0; mt < 4; mt++) {
        const int row = bm + wr * 64 + mt * 16 + (lane >> 2);
#pragma unroll
        for (int nt = 0; nt < 4; nt++) {
            const int col = bn + wc * 32 + nt * 8 + (lane & 3) * 2;
            if (SPLIT_OUT) {
                uint32_t h, l;
                mkfrag(h, l, acc[mt][nt][0], acc[mt][nt][1]);
                *(uint32_t*)(Ch + (size_t)row * 3072 + col) = h;
                *(uint32_t*)(Cl + (size_t)row * 3072 + col) = l;
                mkfrag(h, l, acc[mt][nt][2], acc[mt][nt][3]);
                *(uint32_t*)(Ch + (size_t)(row + 8) * 3072 + col) = h;
                *(uint32_t*)(Cl + (size_t)(row + 8) * 3072 + col) = l;
            } else {
                float b0v = 0.f, b1v = 0.f;
                if (HAS_BIAS) { b0v = __ldg(&bias[col]); b1v = __ldg(&bias[col + 1]); }
                *(float2*)&C[(size_t)row * NCOL + col] =
                    make_float2(acc[mt][nt][0] + b0v, acc[mt][nt][1] + b1v);
                *(float2*)&C[(size_t)(row + 8) * NCOL + col] =
                    make_float2(acc[mt][nt][2] + b0v, acc[mt][nt][3] + b1v);
            }
        }
    }
}

__global__ __launch_bounds__(256, 2) void k_gemm_qkv() {
    gemm_core<true, false, 3072>(g_xs, g_ws, nullptr, g_qkvh, g_qkvl, nullptr);
}
__global__ __launch_bounds__(256, 2) void k_gemm_proj(const float* __restrict__ bias,
                                                      float* __restrict__ out) {
    gemm_core<false, true, 1024>(g_aos, g_wp, out, nullptr, nullptr, bias);
}

// ---------------- flash attention (bf16x3 split), q-tile 128, 8 warps --------
__global__ __launch_bounds__(256, 2) void k_attn() {
    extern __shared__ char smraw[];
    const uint32_t base = (smem_u32(smraw) + 1023u) & ~1023u;
    const uint32_t QH = base, QL = base + 16384;
    const uint32_t KV0 = base + 32768;               // stage s: KV0 + s*32768
    const int tid = threadIdx.x, lane = tid & 31, wid = tid >> 5;
    const int bh = blockIdx.y, q0 = blockIdx.x * 128;
    const size_t tok0 = (size_t)(bh >> 4) * 2048;
    const int qc = (bh & 15) * 64, kcol = 1024 + qc, vcol = 2048 + qc;
    constexpr float CS = SCALE * LOG2E;

    // load Q tiles (hi/lo): 128 rows x 128B each, SW128 swizzled
#pragma unroll
    for (int j = 0; j < 4; j++) {
        int idx = tid + j * 256;
        int r = idx >> 3, c = (idx & 7) * 8;
        size_t off = (tok0 + q0 + r) * 3072 + qc + c;
        uint32_t d = SWZ128((uint32_t)(r * 128 + c * 2));
        sts128(QH + d, *(const uint4*)(g_qkvh + off));
        sts128(QL + d, *(const uint4*)(g_qkvl + off));
    }

#define KV_LOAD(stage, t)                                                       \
    do {                                                                        \
        const uint32_t _kb = KV0 + (stage) * 32768;                             \
        const int _kv0 = (t) * 64;                                              \
        _Pragma("unroll")                                                       \
        for (int _j = 0; _j < 2; _j++) {                                        \
            int _idx = tid + _j * 256;                                          \
            int _r = _idx >> 3, _c = (_idx & 7) * 8;                            \
            size_t _ro = (tok0 + _kv0 + _r) * 3072;                             \
            uint32_t _d = SWZ128((uint32_t)(_r * 128 + _c * 2));                \
            cpa16(_kb + _d,         g_qkvh + _ro + kcol + _c);                  \
            cpa16(_kb + 8192 + _d,  g_qkvl + _ro + kcol + _c);                  \
            cpa16(_kb + 16384 + _d, g_qkvh + _ro + vcol + _c);                  \
            cpa16(_kb + 24576 + _d, g_qkvl + _ro + vcol + _c);                  \
        }                                                                       \
    } while (0)

    KV_LOAD(0, 0); CP_COMMIT();
    __syncthreads();

    // Q fragments to registers
    uint32_t aqh[4][4], aql[4][4];
#pragma unroll
    for (int k = 0; k < 4; k++) {
        int rr = wid * 16 + (lane & 15);
        int cq = k * 16 + ((lane & 16) ? 8 : 0);
        uint32_t d = SWZ128((uint32_t)(rr * 128 + cq * 2));
        ldsm4(aqh[k][0], aqh[k][1], aqh[k][2], aqh[k][3], QH + d);
        ldsm4(aql[k][0], aql[k][1], aql[k][2], aql[k][3], QL + d);
    }

    float o[8][4];
#pragma unroll
    for (int i = 0; i < 8; i++)
#pragma unroll
        for (int j = 0; j < 4; j++) o[i][j] = 0.f;
    float m0 = -1e30f, m1 = -1e30f, l0 = 0.f, l1 = 0.f;

    for (int t = 0; t < 32; t++) {
        CP_WAIT0();
        __syncthreads();
        if (t + 1 < 32) { KV_LOAD((t + 1) & 1, t + 1); CP_COMMIT(); }
        const uint32_t KH = KV0 + (t & 1) * 32768, KL = KH + 8192,
                       VH = KH + 16384, VL = KH + 24576;

        // ---- S = Q K^T (3-term split) ----
        float s[8][4];
#pragma unroll
        for (int i = 0; i < 8; i++)
#pragma unroll
            for (int j = 0; j < 4; j++) s[i][j] = 0.f;
#pragma unroll
        for (int k = 0; k < 4; k++) {
            const int kb = k * 16 + ((lane & 8) ? 8 : 0);
#pragma unroll
            for (int p = 0; p < 4; p++) {
                const int nr = p * 16 + (lane & 7) + ((lane & 16) ? 8 : 0);
                uint32_t d = SWZ128((uint32_t)(nr * 128 + kb * 2));
                uint32_t h0, h1, h2, h3, e0, e1, e2, e3;
                ldsm4(h0, h1, h2, h3, KH + d);
                ldsm4(e0, e1, e2, e3, KL + d);
                mma16816(s[2 * p], aqh[k], h0, h1);
                mma16816(s[2 * p], aqh[k], e0, e1);
                mma16816(s[2 * p], aql[k], h0, h1);
                mma16816(s[2 * p + 1], aqh[k], h2, h3);
                mma16816(s[2 * p + 1], aqh[k], e2, e3);
                mma16816(s[2 * p + 1], aql[k], h2, h3);
            }
        }

        // ---- online softmax in exp2 domain ----
        float mx0 = -1e30f, mx1 = -1e30f;
#pragma unroll
        for (int nt = 0; nt < 8; nt++) {
#pragma unroll
            for (int j = 0; j < 4; j++) s[nt][j] *= CS;
            mx0 = fmaxf(mx0, fmaxf(s[nt][0], s[nt][1]));
            mx1 = fmaxf(mx1, fmaxf(s[nt][2], s[nt][3]));
        }
        mx0 = fmaxf(mx0, __shfl_xor_sync(0xffffffffu, mx0, 1));
        mx0 = fmaxf(mx0, __shfl_xor_sync(0xffffffffu, mx0, 2));
        mx1 = fmaxf(mx1, __shfl_xor_sync(0xffffffffu, mx1, 1));
        mx1 = fmaxf(mx1, __shfl_xor_sync(0xffffffffu, mx1, 2));
        const float mn0 = fmaxf(m0, mx0), mn1 = fmaxf(m1, mx1);
        const float a0 = exp2f(m0 - mn0), a1 = exp2f(m1 - mn1);
        m0 = mn0; m1 = mn1;
        float sum0 = 0.f, sum1 = 0.f;
#pragma unroll
        for (int nt = 0; nt < 8; nt++) {
            s[nt][0] = exp2f(s[nt][0] - mn0);
            s[nt][1] = exp2f(s[nt][1] - mn0);
            s[nt][2] = exp2f(s[nt][2] - mn1);
            s[nt][3] = exp2f(s[nt][3] - mn1);
            sum0 += s[nt][0] + s[nt][1];
            sum1 += s[nt][2] + s[nt][3];
            o[nt][0] *= a0; o[nt][1] *= a0;
            o[nt][2] *= a1; o[nt][3] *= a1;
        }
        sum0 += __shfl_xor_sync(0xffffffffu, sum0, 1);
        sum0 += __shfl_xor_sync(0xffffffffu, sum0, 2);
        sum1 += __shfl_xor_sync(0xffffffffu, sum1, 1);
        sum1 += __shfl_xor_sync(0xffffffffu, sum1, 2);
        l0 = l0 * a0 + sum0;
        l1 = l1 * a1 + sum1;

        // ---- P fragments (hi + residual lo) ----
        uint32_t ph[4][4], pl[4][4];
#pragma unroll
        for (int k = 0; k < 4; k++) {
            mkfrag(ph[k][0], pl[k][0], s[2 * k][0], s[2 * k][1]);
            mkfrag(ph[k][1], pl[k][1], s[2 * k][2], s[2 * k][3]);
            mkfrag(ph[k][2], pl[k][2], s[2 * k + 1][0], s[2 * k + 1][1]);
            mkfrag(ph[k][3], pl[k][3], s[2 * k + 1][2], s[2 * k + 1][3]);
        }

        // ---- O += P V (3-term split) ----
#pragma unroll
        for (int k = 0; k < 4; k++) {
            const int kvr = k * 16 + (lane & 7) + ((lane & 8) ? 8 : 0);
#pragma unroll
            for (int p = 0; p < 4; p++) {
                const int dc = p * 16 + ((lane & 16) ? 8 : 0);
                uint32_t d = SWZ128((uint32_t)(kvr * 128 + dc * 2));
                uint32_t h0, h1, h2, h3, e0, e1, e2, e3;
                ldsm4t(h0, h1, h2, h3, VH + d);
                ldsm4t(e0, e1, e2, e3, VL + d);
                mma16816(o[2 * p], ph[k], h0, h1);
                mma16816(o[2 * p], ph[k], e0, e1);
                mma16816(o[2 * p], pl[k], h0, h1);
                mma16816(o[2 * p + 1], ph[k], h2, h3);
                mma16816(o[2 * p + 1], ph[k], e2, e3);
                mma16816(o[2 * p + 1], pl[k], h2, h3);
            }
        }
    }
#undef KV_LOAD

    // ---- normalize + write split [hi|hi|lo] rows of g_aos ----
    const float inv0 = 1.f / l0, inv1 = 1.f / l1;
    const int rq = q0 + wid * 16 + (lane >> 2);
    __nv_bfloat16* d0 = g_aos + (tok0 + rq) * 3072 + (bh & 15) * 64;
    __nv_bfloat16* d1 = d0 + 8 * 3072;
#pragma unroll
    for (int nt = 0; nt < 8; nt++) {
        const int col = nt * 8 + (lane & 3) * 2;
        uint32_t h, l;
        mkfrag(h, l, o[nt][0] * inv0, o[nt][1] * inv0);
        *(uint32_t*)(d0 + col) = h;
        *(uint32_t*)(d0 + 1024 + col) = h;
        *(uint32_t*)(d0 + 2048 + col) = l;
        mkfrag(h, l, o[nt][2] * inv1, o[nt][3] * inv1);
        *(uint32_t*)(d1 + col) = h;
        *(uint32_t*)(d1 + 1024 + col) = h;
        *(uint32_t*)(d1 + 2048 + col) = l;
    }
}

// ---------------- launch ----------------
extern "C" void kernel_launch(void* const* d_in, const int* in_sizes, int n_in,
                              void* d_out, int out_size) {
    (void)in_sizes; (void)n_in; (void)out_size;
    const float* x      = (const float*)d_in[0];
    const float* w_qkv  = (const float*)d_in[1];
    const float* w_proj = (const float*)d_in[2];
    const float* b_proj = (const float*)d_in[3];
    float* out = (float*)d_out;

    static bool attr_set = false;
    if (!attr_set) {
        cudaFuncSetAttribute(k_gemm_qkv, cudaFuncAttributeMaxDynamicSharedMemorySize, 66560);
        cudaFuncSetAttribute(k_gemm_proj, cudaFuncAttributeMaxDynamicSharedMemorySize, 66560);
        cudaFuncSetAttribute(k_attn, cudaFuncAttributeMaxDynamicSharedMemorySize, 99328);
        attr_set = true;
    }

    k_split_x<<<16384, 256>>>(x);
    k_split_wqkv<<<6144, 256>>>(w_qkv);
    k_split_wproj<<<2048, 256>>>(w_proj);
    k_gemm_qkv<<<dim3(24, 64), 256, 66560>>>();
    k_attn<<<dim3(16, 64), 256, 99328>>>();
    k_gemm_proj<<<dim3(8, 64), 256, 66560>>>(b_proj, out);
}